// round 6
// baseline (speedup 1.0000x reference)
#include <cuda_runtime.h>
#include <cstdint>
#include <math.h>

// Problem constants
#define NWIN 2048
#define NTOK 64
#define CDIM 384
#define NH   12
#define HD   32
#define MTOT (NWIN * NTOK)          // 131072 rows

// ---------------------------------------------------------------------------
// Device scratch
// ---------------------------------------------------------------------------
__device__ float g_x32[(size_t)MTOT * CDIM];           // x pre-rounded to tf32
__device__ float g_qkv[(size_t)MTOT * 3 * CDIM];       // [M,1152] tf32 bits
__device__ float g_attn[(size_t)MTOT * CDIM];          // [M,384]  tf32 bits
__device__ float g_bias[NH * NTOK * NTOK];             // fp32
__device__ float g_wt_qkv[(size_t)3 * CDIM * CDIM];    // [1152,384] K-major tf32
__device__ float g_wt_proj[(size_t)CDIM * CDIM];       // [384,384]  K-major tf32

__device__ __forceinline__ uint32_t f2tf32(float v) {
    uint32_t r;
    asm("cvt.rna.tf32.f32 %0, %1;" : "=r"(r) : "f"(v));
    return r;
}
__device__ __forceinline__ float f2tf32f(float v) { return __uint_as_float(f2tf32(v)); }

__device__ __forceinline__ void mma_tf32(float* d, const uint32_t* a, const uint32_t* b) {
    asm volatile(
        "mma.sync.aligned.m16n8k8.row.col.f32.tf32.tf32.f32 "
        "{%0,%1,%2,%3}, {%4,%5,%6,%7}, {%8,%9}, {%0,%1,%2,%3};"
        : "+f"(d[0]), "+f"(d[1]), "+f"(d[2]), "+f"(d[3])
        : "r"(a[0]), "r"(a[1]), "r"(a[2]), "r"(a[3]), "r"(b[0]), "r"(b[1]));
}
__device__ __forceinline__ uint32_t smem_u32(const void* p) {
    uint32_t a;
    asm("{ .reg .u64 t; cvta.to.shared.u64 t, %1; cvt.u32.u64 %0, t; }" : "=r"(a) : "l"(p));
    return a;
}
__device__ __forceinline__ void cp16(uint32_t dst, const void* src) {
    asm volatile("cp.async.cg.shared.global [%0], [%1], 16;" :: "r"(dst), "l"(src));
}
#define CP_COMMIT() asm volatile("cp.async.commit_group;" ::: "memory")
#define CP_WAIT(N)  asm volatile("cp.async.wait_group %0;" :: "n"(N) : "memory")

// ---------------------------------------------------------------------------
// x -> tf32 pre-round
// ---------------------------------------------------------------------------
__global__ void convert_x_kernel(const float* __restrict__ in) {
    size_t i = ((size_t)blockIdx.x * blockDim.x + threadIdx.x) * 4;
    if (i >= (size_t)MTOT * CDIM) return;
    float4 v = *(const float4*)(in + i);
    float4 o;
    o.x = f2tf32f(v.x); o.y = f2tf32f(v.y); o.z = f2tf32f(v.z); o.w = f2tf32f(v.w);
    *(float4*)(g_x32 + i) = o;
}

// ---------------------------------------------------------------------------
// weight transpose + tf32 round:  out[N,K] = tf32(in[K,N])
// ---------------------------------------------------------------------------
__global__ void transpose_kernel(const float* __restrict__ in, float* __restrict__ out,
                                 int K, int N) {
    __shared__ float tl[32][33];
    int n0 = blockIdx.x * 32, k0 = blockIdx.y * 32;
    int x = threadIdx.x, y = threadIdx.y;
#pragma unroll
    for (int j = y; j < 32; j += 8) tl[j][x] = in[(size_t)(k0 + j) * N + n0 + x];
    __syncthreads();
#pragma unroll
    for (int j = y; j < 32; j += 8) out[(size_t)(n0 + j) * K + k0 + x] = f2tf32f(tl[x][j]);
}

// ---------------------------------------------------------------------------
// relative position bias table (fp32)
// ---------------------------------------------------------------------------
__global__ void bias_kernel(const float* __restrict__ w1, const float* __restrict__ b1,
                            const float* __restrict__ w2, const float* __restrict__ b2) {
    int idx = blockIdx.x * blockDim.x + threadIdx.x;
    if (idx >= NTOK * NTOK) return;
    int n = idx / NTOK, m = idx % NTOK;
    float r0 = (float)((n >> 4) & 3) - (float)((m >> 4) & 3);
    float r1 = (float)((n >> 2) & 3) - (float)((m >> 2) & 3);
    float r2 = (float)(n & 3)        - (float)(m & 3);

    float outh[NH];
#pragma unroll
    for (int h = 0; h < NH; h++) outh[h] = b2[h];
    for (int j = 0; j < 64; j++) {
        float hj = fmaf(r0, w1[j], fmaf(r1, w1[64 + j], fmaf(r2, w1[128 + j], b1[j])));
        hj = fmaxf(hj, 0.0f);
#pragma unroll
        for (int h = 0; h < NH; h++) outh[h] = fmaf(hj, w2[j * NH + h], outh[h]);
    }
#pragma unroll
    for (int h = 0; h < NH; h++) g_bias[h * NTOK * NTOK + idx] = outh[h];
}

// ---------------------------------------------------------------------------
// tf32 mma.sync GEMM v3: CTA tile 256x128, 8 warps (4Mx2N), warp tile 64x64.
// 3-stage cp.async ring; zero CVT in mainloop.
// smem floats: A stages @ st*8192 (3x32KB), B stages @ 24576 + st*4096 (3x16KB)
// ---------------------------------------------------------------------------
#define KC 32
#define NCH (CDIM / KC)   // 12
#define GEMM_SMEM (36864 * 4)   // 144 KB

template <bool ROUND_OUT>
__global__ void __launch_bounds__(256, 1)
gemm_tf32(const float* __restrict__ A, const float* __restrict__ Bt,
          const float* __restrict__ bias, float* __restrict__ out, int ldc) {
    extern __shared__ float dsm[];

    const int t    = threadIdx.x;
    const int wid  = t >> 5, lane = t & 31;
    const int wm   = wid >> 1;         // 0..3 (64-row slab)
    const int wn   = wid & 1;          // 0..1 (64-col slab)
    const int n0   = blockIdx.x * 128;
    const int m0   = blockIdx.y * 256;
    const int lrow = lane >> 2;
    const int lcol = lane & 3;

    const uint32_t sbase = smem_u32(dsm);

    float acc[4][8][4];
#pragma unroll
    for (int i = 0; i < 4; i++)
#pragma unroll
        for (int j = 0; j < 8; j++)
#pragma unroll
            for (int r = 0; r < 4; r++) acc[i][j][r] = 0.0f;

    const int ldr = t >> 3;            // 0..31 base row
    const int ldg = t & 7;             // 16B group

    int rowa[4], rowb[8];
#pragma unroll
    for (int mt = 0; mt < 4; mt++) rowa[mt] = (wm * 64 + mt * 16 + lrow) * 32 + lcol;
#pragma unroll
    for (int nt = 0; nt < 8; nt++) rowb[nt] = (wn * 64 + nt * 8 + lrow) * 32 + lcol;

#define ISSUE(ch, st) do {                                                               \
        int _k0 = (ch) * KC;                                                             \
        _Pragma("unroll")                                                                \
        for (int _i = 0; _i < 8; _i++) {                                                 \
            int _row = ldr + _i * 32;                                                    \
            int _sg  = ldg ^ (_row & 7);                                                 \
            cp16(sbase + (st) * 32768 + (uint32_t)((_row * 32 + _sg * 4) * 4),           \
                 A + (size_t)(m0 + _row) * CDIM + _k0 + ldg * 4);                        \
        }                                                                                \
        _Pragma("unroll")                                                                \
        for (int _i = 0; _i < 4; _i++) {                                                 \
            int _row = ldr + _i * 32;                                                    \
            int _sg  = ldg ^ (_row & 7);                                                 \
            cp16(sbase + 98304 + (st) * 16384 + (uint32_t)((_row * 32 + _sg * 4) * 4),   \
                 Bt + (size_t)(n0 + _row) * CDIM + _k0 + ldg * 4);                       \
        }                                                                                \
        CP_COMMIT();                                                                     \
    } while (0)

#define COMPUTE(st) do {                                                                 \
        const float* As_ = dsm + (st) * 8192;                                            \
        const float* Bs_ = dsm + 24576 + (st) * 4096;                                    \
        _Pragma("unroll")                                                                \
        for (int ks = 0; ks < 4; ks++) {                                                 \
            const int go0 = ((2 * ks) ^ lrow) * 4;                                       \
            const int go1 = ((2 * ks + 1) ^ lrow) * 4;                                   \
            uint32_t afr[4][4], bfr[8][2];                                               \
            _Pragma("unroll")                                                            \
            for (int mt = 0; mt < 4; mt++) {                                             \
                afr[mt][0] = __float_as_uint(As_[rowa[mt] + go0]);                       \
                afr[mt][1] = __float_as_uint(As_[rowa[mt] + 256 + go0]);                 \
                afr[mt][2] = __float_as_uint(As_[rowa[mt] + go1]);                       \
                afr[mt][3] = __float_as_uint(As_[rowa[mt] + 256 + go1]);                 \
            }                                                                            \
            _Pragma("unroll")                                                            \
            for (int nt = 0; nt < 8; nt++) {                                             \
                bfr[nt][0] = __float_as_uint(Bs_[rowb[nt] + go0]);                       \
                bfr[nt][1] = __float_as_uint(Bs_[rowb[nt] + go1]);                       \
            }                                                                            \
            _Pragma("unroll")                                                            \
            for (int mt = 0; mt < 4; mt++)                                               \
                _Pragma("unroll")                                                        \
                for (int nt = 0; nt < 8; nt++)                                           \
                    mma_tf32(acc[mt][nt], afr[mt], bfr[nt]);                             \
        }                                                                                \
    } while (0)

#define STEP(c, st, stnext) do {                                                         \
        if ((c) == NCH - 1) { CP_WAIT(0); } else { CP_WAIT(1); }                         \
        __syncthreads();                                                                 \
        if ((c) + 2 < NCH) ISSUE((c) + 2, stnext);                                       \
        COMPUTE(st);                                                                     \
        __syncthreads();                                                                 \
    } while (0)

    ISSUE(0, 0);
    ISSUE(1, 1);
#pragma unroll
    for (int c3 = 0; c3 < NCH; c3 += 3) {
        STEP(c3 + 0, 0, 2);
        STEP(c3 + 1, 1, 0);
        STEP(c3 + 2, 2, 1);
    }

#pragma unroll
    for (int mt = 0; mt < 4; mt++) {
#pragma unroll
        for (int nt = 0; nt < 8; nt++) {
            int row = m0 + wm * 64 + mt * 16 + lrow;
            int col = n0 + wn * 64 + nt * 8 + lcol * 2;
            float2 bv = *(const float2*)(bias + col);
            float2 o0, o1;
            if (ROUND_OUT) {
                o0.x = f2tf32f(acc[mt][nt][0] + bv.x); o0.y = f2tf32f(acc[mt][nt][1] + bv.y);
                o1.x = f2tf32f(acc[mt][nt][2] + bv.x); o1.y = f2tf32f(acc[mt][nt][3] + bv.y);
            } else {
                o0.x = acc[mt][nt][0] + bv.x; o0.y = acc[mt][nt][1] + bv.y;
                o1.x = acc[mt][nt][2] + bv.x; o1.y = acc[mt][nt][3] + bv.y;
            }
            *(float2*)(out + (size_t)row * ldc + col)       = o0;
            *(float2*)(out + (size_t)(row + 8) * ldc + col) = o1;
        }
    }
#undef STEP
#undef COMPUTE
#undef ISSUE
}

// ---------------------------------------------------------------------------
// Tensor-core attention v2: cp.async ping-pong prefetch of q/k/v per head.
// Block = 1 window, 256 thr = 2 teams x 4 warps; team does 6 heads.
// Team smem (floats):
//   qs[2][64*36]=4608, ks[2][64*36]=4608, vst[2][64*36]=4608,
//   vt[32*68]=2176, Ss[64*68]=4352   -> 20352 floats = 79.5 KB
// ---------------------------------------------------------------------------
#define TEAM_F 20352
#define ATTN_SMEM (2 * TEAM_F * 4)   // 159 KB

__global__ void __launch_bounds__(256, 1)
attn_kernel() {
    extern __shared__ float dsm[];
    const int b    = blockIdx.x;
    const int t    = threadIdx.x;
    const int team = t >> 7;
    const int lt   = t & 127;
    const int w    = lt >> 5;
    const int lane = t & 31;
    const int lrow = lane >> 2;
    const int lcol = lane & 3;

    float* tb  = dsm + team * TEAM_F;
    float* qs0 = tb;                  // [2][64*36]
    float* ks0 = tb + 2 * 2304;
    float* vst = tb + 4 * 2304;       // [2][64*36]
    float* vt  = tb + 6 * 2304;       // [32][68]
    float* Ss  = vt + 32 * 68;        // [64][68]

    const uint32_t tbase = smem_u32(tb);

    const float scale = 0.17677669529663687f;  // 1/sqrt(32)
    const float* qkvb = g_qkv + (size_t)b * NTOK * (3 * CDIM);

    // prefetch loader: thread lt covers rows lt>>3 + {0,16,32,48}, group lt&7
    const int prow = lt >> 3;   // 0..15
    const int pg   = lt & 7;    // 16B group

#define ISSUE_HEAD(h, st) do {                                                            \
        int _qo = (h) * HD + pg * 4;                                                      \
        int _ko = CDIM + (h) * HD + pg * 4;                                               \
        int _vo = 2 * CDIM + (h) * HD + pg * 4;                                           \
        _Pragma("unroll")                                                                 \
        for (int _i = 0; _i < 4; _i++) {                                                  \
            int _n = prow + _i * 16;                                                      \
            const float* _src = qkvb + (size_t)_n * (3 * CDIM);                           \
            uint32_t _d = (uint32_t)(((st) * 2304 + _n * 36 + pg * 4) * 4);               \
            cp16(tbase + _d,               _src + _qo);                                   \
            cp16(tbase + 2 * 9216 + _d,    _src + _ko);                                   \
            cp16(tbase + 4 * 9216 + _d,    _src + _vo);                                   \
        }                                                                                 \
        CP_COMMIT();                                                                      \
    } while (0)

    ISSUE_HEAD(team, 0);

    for (int hi = 0; hi < 6; hi++) {
        const int h  = hi * 2 + team;
        const int st = hi & 1;
        const float* qs = qs0 + st * 2304;
        const float* ks = ks0 + st * 2304;
        const float* vs = vst + st * 2304;

        CP_WAIT(0);
        __syncthreads();

        // transpose v: vst[n][d] -> vt[d][n]
#pragma unroll
        for (int i = 0; i < 4; i++) {
            int idx = lt + i * 128;           // 0..511
            int n = idx >> 3, c4 = idx & 7;
            float4 vv = *(const float4*)(vs + n * 36 + c4 * 4);
            int d0 = c4 * 4;
            vt[(d0 + 0) * 68 + n] = vv.x;
            vt[(d0 + 1) * 68 + n] = vv.y;
            vt[(d0 + 2) * 68 + n] = vv.z;
            vt[(d0 + 3) * 68 + n] = vv.w;
        }
        __syncthreads();

        // prefetch next head
        if (hi < 5) ISSUE_HEAD(h + 2, st ^ 1);

        // ---- S = Q K^T
        float sacc[8][4];
#pragma unroll
        for (int nt = 0; nt < 8; nt++)
#pragma unroll
            for (int r = 0; r < 4; r++) sacc[nt][r] = 0.0f;

#pragma unroll
        for (int kc = 0; kc < 4; kc++) {
            const int kk = kc * 8;
            int row0 = w * 16 + lrow;
            uint32_t af[4];
            af[0] = __float_as_uint(qs[row0 * 36 + kk + lcol]);
            af[1] = __float_as_uint(qs[(row0 + 8) * 36 + kk + lcol]);
            af[2] = __float_as_uint(qs[row0 * 36 + kk + 4 + lcol]);
            af[3] = __float_as_uint(qs[(row0 + 8) * 36 + kk + 4 + lcol]);
#pragma unroll
            for (int nt = 0; nt < 8; nt++) {
                int krow = nt * 8 + lrow;
                uint32_t bf[2];
                bf[0] = __float_as_uint(ks[krow * 36 + kk + lcol]);
                bf[1] = __float_as_uint(ks[krow * 36 + kk + 4 + lcol]);
                mma_tf32(sacc[nt], af, bf);
            }
        }
        const float* bh = g_bias + h * NTOK * NTOK;
        {
            int row = w * 16 + lrow;
#pragma unroll
            for (int nt = 0; nt < 8; nt++) {
                int col = nt * 8 + lcol * 2;
                float2 b0 = *(const float2*)(bh + row * 64 + col);
                float2 b1 = *(const float2*)(bh + (row + 8) * 64 + col);
                Ss[row * 68 + col]           = fmaf(sacc[nt][0], scale, b0.x);
                Ss[row * 68 + col + 1]       = fmaf(sacc[nt][1], scale, b0.y);
                Ss[(row + 8) * 68 + col]     = fmaf(sacc[nt][2], scale, b1.x);
                Ss[(row + 8) * 68 + col + 1] = fmaf(sacc[nt][3], scale, b1.y);
            }
        }
        __syncthreads();

        // ---- softmax: 2 threads per row
        {
            int r = lt >> 1;
            float* Sr = Ss + r * 68 + (lt & 1) * 32;
            float mx = -1e30f;
#pragma unroll 8
            for (int m = 0; m < 32; m++) mx = fmaxf(mx, Sr[m]);
            mx = fmaxf(mx, __shfl_xor_sync(0xFFFFFFFFu, mx, 1));
            float sum = 0.0f;
#pragma unroll 8
            for (int m = 0; m < 32; m++) { float e = __expf(Sr[m] - mx); Sr[m] = e; sum += e; }
            sum += __shfl_xor_sync(0xFFFFFFFFu, sum, 1);
            float inv = 1.0f / sum;
#pragma unroll 8
            for (int m = 0; m < 32; m++) Sr[m] *= inv;
        }
        __syncthreads();

        // ---- O = P V
        float oacc[4][4];
#pragma unroll
        for (int nt = 0; nt < 4; nt++)
#pragma unroll
            for (int r = 0; r < 4; r++) oacc[nt][r] = 0.0f;

#pragma unroll
        for (int kc = 0; kc < 8; kc++) {
            const int kk = kc * 8;
            int row0 = w * 16 + lrow;
            uint32_t pf[4];
            pf[0] = f2tf32(Ss[row0 * 68 + kk + lcol]);
            pf[1] = f2tf32(Ss[(row0 + 8) * 68 + kk + lcol]);
            pf[2] = f2tf32(Ss[row0 * 68 + kk + 4 + lcol]);
            pf[3] = f2tf32(Ss[(row0 + 8) * 68 + kk + 4 + lcol]);
#pragma unroll
            for (int nt = 0; nt < 4; nt++) {
                int dd = nt * 8 + lrow;
                uint32_t vf[2];
                vf[0] = __float_as_uint(vt[dd * 68 + kk + lcol]);
                vf[1] = __float_as_uint(vt[dd * 68 + kk + 4 + lcol]);
                mma_tf32(oacc[nt], pf, vf);
            }
        }
        {
            float* og = g_attn + (size_t)b * NTOK * CDIM + h * HD;
            int row = w * 16 + lrow;
#pragma unroll
            for (int nt = 0; nt < 4; nt++) {
                int col = nt * 8 + lcol * 2;
                float2 o0 = make_float2(f2tf32f(oacc[nt][0]), f2tf32f(oacc[nt][1]));
                float2 o1 = make_float2(f2tf32f(oacc[nt][2]), f2tf32f(oacc[nt][3]));
                *(float2*)(og + (size_t)row * CDIM + col)       = o0;
                *(float2*)(og + (size_t)(row + 8) * CDIM + col) = o1;
            }
        }
    }
#undef ISSUE_HEAD
}

// ---------------------------------------------------------------------------
extern "C" void kernel_launch(void* const* d_in, const int* in_sizes, int n_in,
                              void* d_out, int out_size) {
    const float* x      = (const float*)d_in[0];
    const float* qkv_w  = (const float*)d_in[1];
    const float* qkv_b  = (const float*)d_in[2];
    const float* proj_w = (const float*)d_in[3];
    const float* proj_b = (const float*)d_in[4];
    const float* mlp_w1 = (const float*)d_in[5];
    const float* mlp_b1 = (const float*)d_in[6];
    const float* mlp_w2 = (const float*)d_in[7];
    const float* mlp_b2 = (const float*)d_in[8];

    float* wt_qkv;  cudaGetSymbolAddress((void**)&wt_qkv,  g_wt_qkv);
    float* wt_proj; cudaGetSymbolAddress((void**)&wt_proj, g_wt_proj);
    float* qkv;     cudaGetSymbolAddress((void**)&qkv,     g_qkv);
    float* attn;    cudaGetSymbolAddress((void**)&attn,    g_attn);
    float* x32;     cudaGetSymbolAddress((void**)&x32,     g_x32);

    convert_x_kernel<<<(MTOT * CDIM / 4 + 255) / 256, 256>>>(x);
    transpose_kernel<<<dim3(3 * CDIM / 32, CDIM / 32), dim3(32, 8)>>>(qkv_w, wt_qkv, CDIM, 3 * CDIM);
    transpose_kernel<<<dim3(CDIM / 32, CDIM / 32), dim3(32, 8)>>>(proj_w, wt_proj, CDIM, CDIM);
    bias_kernel<<<16, 256>>>(mlp_w1, mlp_b1, mlp_w2, mlp_b2);

    cudaFuncSetAttribute(gemm_tf32<true>,  cudaFuncAttributeMaxDynamicSharedMemorySize, GEMM_SMEM);
    cudaFuncSetAttribute(gemm_tf32<false>, cudaFuncAttributeMaxDynamicSharedMemorySize, GEMM_SMEM);
    cudaFuncSetAttribute(attn_kernel, cudaFuncAttributeMaxDynamicSharedMemorySize, ATTN_SMEM);

    // QKV GEMM: [131072,384] @ [384,1152] -> tf32-rounded qkv
    gemm_tf32<true><<<dim3(9, MTOT / 256), 256, GEMM_SMEM>>>(x32, wt_qkv, qkv_b, qkv, 3 * CDIM);

    // attention (tensor cores, cp.async ping-pong) -> tf32-rounded attn
    attn_kernel<<<NWIN, 256, ATTN_SMEM>>>();

    // projection GEMM: [131072,384] @ [384,384] -> d_out (fp32)
    gemm_tf32<false><<<dim3(3, MTOT / 256), 256, GEMM_SMEM>>>(attn, wt_proj, proj_b, (float*)d_out, CDIM);
}

// round 7
// speedup vs baseline: 1.0951x; 1.0951x over previous
#include <cuda_runtime.h>
#include <cstdint>
#include <math.h>

// Problem constants
#define NWIN 2048
#define NTOK 64
#define CDIM 384
#define NH   12
#define HD   32
#define MTOT (NWIN * NTOK)          // 131072 rows

// ---------------------------------------------------------------------------
// Device scratch
// ---------------------------------------------------------------------------
__device__ float g_x32[(size_t)MTOT * CDIM];           // x pre-rounded to tf32
__device__ float g_qkv[(size_t)MTOT * 3 * CDIM];       // [M,1152] tf32 bits
__device__ float g_attn[(size_t)MTOT * CDIM];          // [M,384]  tf32 bits
__device__ float g_bias[NH * NTOK * NTOK];             // fp32
__device__ float g_wt_qkv[(size_t)3 * CDIM * CDIM];    // [1152,384] K-major tf32
__device__ float g_wt_proj[(size_t)CDIM * CDIM];       // [384,384]  K-major tf32

__device__ __forceinline__ uint32_t f2tf32(float v) {
    uint32_t r;
    asm("cvt.rna.tf32.f32 %0, %1;" : "=r"(r) : "f"(v));
    return r;
}
__device__ __forceinline__ float f2tf32f(float v) { return __uint_as_float(f2tf32(v)); }

__device__ __forceinline__ void mma_tf32(float* d, const uint32_t* a, const uint32_t* b) {
    asm volatile(
        "mma.sync.aligned.m16n8k8.row.col.f32.tf32.tf32.f32 "
        "{%0,%1,%2,%3}, {%4,%5,%6,%7}, {%8,%9}, {%0,%1,%2,%3};"
        : "+f"(d[0]), "+f"(d[1]), "+f"(d[2]), "+f"(d[3])
        : "r"(a[0]), "r"(a[1]), "r"(a[2]), "r"(a[3]), "r"(b[0]), "r"(b[1]));
}
__device__ __forceinline__ uint32_t smem_u32(const void* p) {
    uint32_t a;
    asm("{ .reg .u64 t; cvta.to.shared.u64 t, %1; cvt.u32.u64 %0, t; }" : "=r"(a) : "l"(p));
    return a;
}
__device__ __forceinline__ void cp16(uint32_t dst, const void* src) {
    asm volatile("cp.async.cg.shared.global [%0], [%1], 16;" :: "r"(dst), "l"(src));
}
#define CP_COMMIT() asm volatile("cp.async.commit_group;" ::: "memory")
#define CP_WAIT(N)  asm volatile("cp.async.wait_group %0;" :: "n"(N) : "memory")

// ---------------------------------------------------------------------------
// x -> tf32 pre-round
// ---------------------------------------------------------------------------
__global__ void convert_x_kernel(const float* __restrict__ in) {
    size_t i = ((size_t)blockIdx.x * blockDim.x + threadIdx.x) * 4;
    if (i >= (size_t)MTOT * CDIM) return;
    float4 v = *(const float4*)(in + i);
    float4 o;
    o.x = f2tf32f(v.x); o.y = f2tf32f(v.y); o.z = f2tf32f(v.z); o.w = f2tf32f(v.w);
    *(float4*)(g_x32 + i) = o;
}

// ---------------------------------------------------------------------------
// weight transpose + tf32 round:  out[N,K] = tf32(in[K,N])
// ---------------------------------------------------------------------------
__global__ void transpose_kernel(const float* __restrict__ in, float* __restrict__ out,
                                 int K, int N) {
    __shared__ float tl[32][33];
    int n0 = blockIdx.x * 32, k0 = blockIdx.y * 32;
    int x = threadIdx.x, y = threadIdx.y;
#pragma unroll
    for (int j = y; j < 32; j += 8) tl[j][x] = in[(size_t)(k0 + j) * N + n0 + x];
    __syncthreads();
#pragma unroll
    for (int j = y; j < 32; j += 8) out[(size_t)(n0 + j) * K + k0 + x] = f2tf32f(tl[x][j]);
}

// ---------------------------------------------------------------------------
// relative position bias table (fp32), weights staged in smem
// ---------------------------------------------------------------------------
__global__ void bias_kernel(const float* __restrict__ w1, const float* __restrict__ b1,
                            const float* __restrict__ w2, const float* __restrict__ b2) {
    __shared__ float sw1[192], sb1[64], sw2[768], sb2[12];
    int tid = threadIdx.x;
    if (tid < 192) sw1[tid] = w1[tid];
    if (tid < 64)  sb1[tid] = b1[tid];
    for (int i = tid; i < 768; i += blockDim.x) sw2[i] = w2[i];
    if (tid < 12)  sb2[tid] = b2[tid];
    __syncthreads();

    int idx = blockIdx.x * blockDim.x + tid;
    if (idx >= NTOK * NTOK) return;
    int n = idx / NTOK, m = idx % NTOK;
    float r0 = (float)((n >> 4) & 3) - (float)((m >> 4) & 3);
    float r1 = (float)((n >> 2) & 3) - (float)((m >> 2) & 3);
    float r2 = (float)(n & 3)        - (float)(m & 3);

    float outh[NH];
#pragma unroll
    for (int h = 0; h < NH; h++) outh[h] = sb2[h];
    for (int j = 0; j < 64; j++) {
        float hj = fmaf(r0, sw1[j], fmaf(r1, sw1[64 + j], fmaf(r2, sw1[128 + j], sb1[j])));
        hj = fmaxf(hj, 0.0f);
#pragma unroll
        for (int h = 0; h < NH; h++) outh[h] = fmaf(hj, sw2[j * NH + h], outh[h]);
    }
#pragma unroll
    for (int h = 0; h < NH; h++) g_bias[h * NTOK * NTOK + idx] = outh[h];
}

// ---------------------------------------------------------------------------
// tf32 mma.sync GEMM (R5 config): CTA 128x128, 8 warps (2Mx4N), warp 64x32,
// 3-stage cp.async ring, zero CVT in mainloop.
// ---------------------------------------------------------------------------
#define KC 32
#define NCH (CDIM / KC)   // 12
#define GEMM_SMEM (24576 * 4)   // 96 KB

template <bool ROUND_OUT>
__global__ void __launch_bounds__(256, 2)
gemm_tf32(const float* __restrict__ A, const float* __restrict__ Bt,
          const float* __restrict__ bias, float* __restrict__ out, int ldc) {
    extern __shared__ float dsm[];

    const int t    = threadIdx.x;
    const int wid  = t >> 5, lane = t & 31;
    const int wm   = wid & 1;
    const int wn   = wid >> 1;
    const int n0   = blockIdx.x * 128;
    const int m0   = blockIdx.y * 128;
    const int lrow = lane >> 2;
    const int lcol = lane & 3;

    const uint32_t sbase = smem_u32(dsm);

    float acc[4][4][4];
#pragma unroll
    for (int i = 0; i < 4; i++)
#pragma unroll
        for (int j = 0; j < 4; j++)
#pragma unroll
            for (int r = 0; r < 4; r++) acc[i][j][r] = 0.0f;

    const int ldr = t >> 3;
    const int ldg = t & 7;

    int rowa[4], rowb[4];
#pragma unroll
    for (int mt = 0; mt < 4; mt++) rowa[mt] = (wm * 64 + mt * 16 + lrow) * 32 + lcol;
#pragma unroll
    for (int nt = 0; nt < 4; nt++) rowb[nt] = (wn * 32 + nt * 8 + lrow) * 32 + lcol;

#define ISSUE(ch, st) do {                                                              \
        int _k0 = (ch) * KC;                                                            \
        _Pragma("unroll")                                                               \
        for (int _i = 0; _i < 4; _i++) {                                                \
            int _row = ldr + _i * 32;                                                   \
            int _sg  = ldg ^ (_row & 7);                                                \
            uint32_t _off = (uint32_t)((st) * 16384 + (_row * 32 + _sg * 4) * 4);       \
            cp16(sbase + _off,         A  + (size_t)(m0 + _row) * CDIM + _k0 + ldg * 4); \
            cp16(sbase + 49152 + _off, Bt + (size_t)(n0 + _row) * CDIM + _k0 + ldg * 4); \
        }                                                                               \
        CP_COMMIT();                                                                    \
    } while (0)

#define COMPUTE(st) do {                                                                \
        const float* As_ = dsm + (st) * 4096;                                           \
        const float* Bs_ = dsm + 12288 + (st) * 4096;                                   \
        _Pragma("unroll")                                                               \
        for (int ks = 0; ks < 4; ks++) {                                                \
            const int go0 = ((2 * ks) ^ lrow) * 4;                                      \
            const int go1 = ((2 * ks + 1) ^ lrow) * 4;                                  \
            uint32_t afr[4][4], bfr[4][2];                                              \
            _Pragma("unroll")                                                           \
            for (int mt = 0; mt < 4; mt++) {                                            \
                afr[mt][0] = __float_as_uint(As_[rowa[mt] + go0]);                      \
                afr[mt][1] = __float_as_uint(As_[rowa[mt] + 256 + go0]);                \
                afr[mt][2] = __float_as_uint(As_[rowa[mt] + go1]);                      \
                afr[mt][3] = __float_as_uint(As_[rowa[mt] + 256 + go1]);                \
            }                                                                           \
            _Pragma("unroll")                                                           \
            for (int nt = 0; nt < 4; nt++) {                                            \
                bfr[nt][0] = __float_as_uint(Bs_[rowb[nt] + go0]);                      \
                bfr[nt][1] = __float_as_uint(Bs_[rowb[nt] + go1]);                      \
            }                                                                           \
            _Pragma("unroll")                                                           \
            for (int mt = 0; mt < 4; mt++)                                              \
                _Pragma("unroll")                                                       \
                for (int nt = 0; nt < 4; nt++)                                          \
                    mma_tf32(acc[mt][nt], afr[mt], bfr[nt]);                            \
        }                                                                               \
    } while (0)

#define STEP(c, st, stnext) do {                                                        \
        if ((c) == NCH - 1) { CP_WAIT(0); } else { CP_WAIT(1); }                        \
        __syncthreads();                                                                \
        if ((c) + 2 < NCH) ISSUE((c) + 2, stnext);                                      \
        COMPUTE(st);                                                                    \
    } while (0)

    ISSUE(0, 0);
    ISSUE(1, 1);
#pragma unroll
    for (int c3 = 0; c3 < NCH; c3 += 3) {
        STEP(c3 + 0, 0, 2);
        STEP(c3 + 1, 1, 0);
        STEP(c3 + 2, 2, 1);
    }

#pragma unroll
    for (int mt = 0; mt < 4; mt++) {
#pragma unroll
        for (int nt = 0; nt < 4; nt++) {
            int row = m0 + wm * 64 + mt * 16 + lrow;
            int col = n0 + wn * 32 + nt * 8 + lcol * 2;
            float2 bv = *(const float2*)(bias + col);
            float2 o0, o1;
            if (ROUND_OUT) {
                o0.x = f2tf32f(acc[mt][nt][0] + bv.x); o0.y = f2tf32f(acc[mt][nt][1] + bv.y);
                o1.x = f2tf32f(acc[mt][nt][2] + bv.x); o1.y = f2tf32f(acc[mt][nt][3] + bv.y);
            } else {
                o0.x = acc[mt][nt][0] + bv.x; o0.y = acc[mt][nt][1] + bv.y;
                o1.x = acc[mt][nt][2] + bv.x; o1.y = acc[mt][nt][3] + bv.y;
            }
            *(float2*)(out + (size_t)row * ldc + col)       = o0;
            *(float2*)(out + (size_t)(row + 8) * ldc + col) = o1;
        }
    }
#undef STEP
#undef COMPUTE
#undef ISSUE
}

// ---------------------------------------------------------------------------
// Tensor-core attention v3: register-resident softmax + shfl repack.
// Block = 1 window, 256 thr = 2 teams x 4 warps; team does 6 heads.
// Warp owns 16 rows of S (all 64 cols) -> softmax warp-private, no smem S.
// Team smem (floats): qs[64*36]=2304, ks[64*36]=2304, vt[32*68]=2176 = 6784
// ---------------------------------------------------------------------------
#define TEAM_F 6784
#define ATTN_SMEM (2 * TEAM_F * 4)   // 53 KB

__global__ void __launch_bounds__(256, 2)
attn_kernel() {
    extern __shared__ float dsm[];
    const int b    = blockIdx.x;
    const int t    = threadIdx.x;
    const int team = t >> 7;
    const int lt   = t & 127;
    const int w    = lt >> 5;
    const int lane = t & 31;
    const int lrow = lane >> 2;
    const int lcol = lane & 3;

    float* qs = dsm + team * TEAM_F;   // [64][36]
    float* ks = qs + 64 * 36;          // [64][36]
    float* vt = ks + 64 * 36;          // [32][68]  (d, m)

    const float scale = 0.17677669529663687f;  // 1/sqrt(32)
    const float* qkvb = g_qkv + (size_t)b * NTOK * (3 * CDIM);

    const int row0 = w * 16 + lrow;    // warp's S row (and +8)

    for (int hi = 0; hi < 6; hi++) {
        const int h = hi * 2 + team;
        const int qoff = h * HD, koff = CDIM + h * HD, voff = 2 * CDIM + h * HD;

        // load q,k row-major; v transposed
        for (int i = lt; i < 512; i += 128) {
            int n = i >> 3, c4 = i & 7;
            const float* rowp = qkvb + (size_t)n * (3 * CDIM);
            float4 qv = *(const float4*)(rowp + qoff + c4 * 4);
            float4 kv = *(const float4*)(rowp + koff + c4 * 4);
            float4 vv = *(const float4*)(rowp + voff + c4 * 4);
            float* qd = qs + n * 36 + c4 * 4;
            float* kd = ks + n * 36 + c4 * 4;
            qd[0] = qv.x; qd[1] = qv.y; qd[2] = qv.z; qd[3] = qv.w;
            kd[0] = kv.x; kd[1] = kv.y; kd[2] = kv.z; kd[3] = kv.w;
            int d0 = c4 * 4;
            vt[(d0 + 0) * 68 + n] = vv.x;
            vt[(d0 + 1) * 68 + n] = vv.y;
            vt[(d0 + 2) * 68 + n] = vv.z;
            vt[(d0 + 3) * 68 + n] = vv.w;
        }
        __syncthreads();

        // ---- S = Q K^T  (warp: rows row0/row0+8, all 64 cols)
        float sacc[8][4];
#pragma unroll
        for (int nt = 0; nt < 8; nt++)
#pragma unroll
            for (int r = 0; r < 4; r++) sacc[nt][r] = 0.0f;

#pragma unroll
        for (int kc = 0; kc < 4; kc++) {
            const int kk = kc * 8;
            uint32_t af[4];
            af[0] = __float_as_uint(qs[row0 * 36 + kk + lcol]);
            af[1] = __float_as_uint(qs[(row0 + 8) * 36 + kk + lcol]);
            af[2] = __float_as_uint(qs[row0 * 36 + kk + 4 + lcol]);
            af[3] = __float_as_uint(qs[(row0 + 8) * 36 + kk + 4 + lcol]);
#pragma unroll
            for (int nt = 0; nt < 8; nt++) {
                int krow = nt * 8 + lrow;
                uint32_t bf[2];
                bf[0] = __float_as_uint(ks[krow * 36 + kk + lcol]);
                bf[1] = __float_as_uint(ks[krow * 36 + kk + 4 + lcol]);
                mma_tf32(sacc[nt], af, bf);
            }
        }

        // ---- scale + bias (in registers)
        const float* bh = g_bias + h * NTOK * NTOK;
#pragma unroll
        for (int nt = 0; nt < 8; nt++) {
            int col = nt * 8 + lcol * 2;
            float2 b0 = *(const float2*)(bh + row0 * 64 + col);
            float2 b1 = *(const float2*)(bh + (row0 + 8) * 64 + col);
            sacc[nt][0] = fmaf(sacc[nt][0], scale, b0.x);
            sacc[nt][1] = fmaf(sacc[nt][1], scale, b0.y);
            sacc[nt][2] = fmaf(sacc[nt][2], scale, b1.x);
            sacc[nt][3] = fmaf(sacc[nt][3], scale, b1.y);
        }

        // ---- register softmax (rows row0 / row0+8; reduce across 4 lanes)
        {
            float mx0 = -1e30f, mx1 = -1e30f;
#pragma unroll
            for (int nt = 0; nt < 8; nt++) {
                mx0 = fmaxf(mx0, fmaxf(sacc[nt][0], sacc[nt][1]));
                mx1 = fmaxf(mx1, fmaxf(sacc[nt][2], sacc[nt][3]));
            }
            mx0 = fmaxf(mx0, __shfl_xor_sync(0xFFFFFFFFu, mx0, 1));
            mx0 = fmaxf(mx0, __shfl_xor_sync(0xFFFFFFFFu, mx0, 2));
            mx1 = fmaxf(mx1, __shfl_xor_sync(0xFFFFFFFFu, mx1, 1));
            mx1 = fmaxf(mx1, __shfl_xor_sync(0xFFFFFFFFu, mx1, 2));
            float s0 = 0.0f, s1 = 0.0f;
#pragma unroll
            for (int nt = 0; nt < 8; nt++) {
                sacc[nt][0] = __expf(sacc[nt][0] - mx0); s0 += sacc[nt][0];
                sacc[nt][1] = __expf(sacc[nt][1] - mx0); s0 += sacc[nt][1];
                sacc[nt][2] = __expf(sacc[nt][2] - mx1); s1 += sacc[nt][2];
                sacc[nt][3] = __expf(sacc[nt][3] - mx1); s1 += sacc[nt][3];
            }
            s0 += __shfl_xor_sync(0xFFFFFFFFu, s0, 1);
            s0 += __shfl_xor_sync(0xFFFFFFFFu, s0, 2);
            s1 += __shfl_xor_sync(0xFFFFFFFFu, s1, 1);
            s1 += __shfl_xor_sync(0xFFFFFFFFu, s1, 2);
            float i0 = 1.0f / s0, i1 = 1.0f / s1;
#pragma unroll
            for (int nt = 0; nt < 8; nt++) {
                sacc[nt][0] *= i0; sacc[nt][1] *= i0;
                sacc[nt][2] *= i1; sacc[nt][3] *= i1;
            }
        }

        // cvt P to tf32 bits (still accumulator layout)
        uint32_t pc[8][4];
#pragma unroll
        for (int nt = 0; nt < 8; nt++)
#pragma unroll
            for (int r = 0; r < 4; r++) pc[nt][r] = f2tf32(sacc[nt][r]);

        // ---- repack accumulator-layout P -> A-fragments via shfl
        // target a0=(row0, kk+lcol): src lane lrow*4+(lcol>>1), reg parity lcol&1
        const int src  = lrow * 4 + (lcol >> 1);
        const int src2 = src + 2;
        const int par  = lcol & 1;
        uint32_t pf[8][4];
#pragma unroll
        for (int kc = 0; kc < 8; kc++) {
            uint32_t x0 = __shfl_sync(0xFFFFFFFFu, pc[kc][0], src);
            uint32_t x1 = __shfl_sync(0xFFFFFFFFu, pc[kc][1], src);
            uint32_t x2 = __shfl_sync(0xFFFFFFFFu, pc[kc][2], src);
            uint32_t x3 = __shfl_sync(0xFFFFFFFFu, pc[kc][3], src);
            uint32_t y0 = __shfl_sync(0xFFFFFFFFu, pc[kc][0], src2);
            uint32_t y1 = __shfl_sync(0xFFFFFFFFu, pc[kc][1], src2);
            uint32_t y2 = __shfl_sync(0xFFFFFFFFu, pc[kc][2], src2);
            uint32_t y3 = __shfl_sync(0xFFFFFFFFu, pc[kc][3], src2);
            pf[kc][0] = par ? x1 : x0;
            pf[kc][1] = par ? x3 : x2;
            pf[kc][2] = par ? y1 : y0;
            pf[kc][3] = par ? y3 : y2;
        }

        // ---- O = P V
        float oacc[4][4];
#pragma unroll
        for (int nt = 0; nt < 4; nt++)
#pragma unroll
            for (int r = 0; r < 4; r++) oacc[nt][r] = 0.0f;

#pragma unroll
        for (int kc = 0; kc < 8; kc++) {
            const int kk = kc * 8;
#pragma unroll
            for (int nt = 0; nt < 4; nt++) {
                int dd = nt * 8 + lrow;
                uint32_t vf[2];
                vf[0] = __float_as_uint(vt[dd * 68 + kk + lcol]);
                vf[1] = __float_as_uint(vt[dd * 68 + kk + 4 + lcol]);
                mma_tf32(oacc[nt], pf[kc], vf);
            }
        }
        {
            float* og = g_attn + (size_t)b * NTOK * CDIM + h * HD;
#pragma unroll
            for (int nt = 0; nt < 4; nt++) {
                int col = nt * 8 + lcol * 2;
                float2 o0 = make_float2(f2tf32f(oacc[nt][0]), f2tf32f(oacc[nt][1]));
                float2 o1 = make_float2(f2tf32f(oacc[nt][2]), f2tf32f(oacc[nt][3]));
                *(float2*)(og + (size_t)row0 * CDIM + col)       = o0;
                *(float2*)(og + (size_t)(row0 + 8) * CDIM + col) = o1;
            }
        }
        __syncthreads();
    }
}

// ---------------------------------------------------------------------------
extern "C" void kernel_launch(void* const* d_in, const int* in_sizes, int n_in,
                              void* d_out, int out_size) {
    const float* x      = (const float*)d_in[0];
    const float* qkv_w  = (const float*)d_in[1];
    const float* qkv_b  = (const float*)d_in[2];
    const float* proj_w = (const float*)d_in[3];
    const float* proj_b = (const float*)d_in[4];
    const float* mlp_w1 = (const float*)d_in[5];
    const float* mlp_b1 = (const float*)d_in[6];
    const float* mlp_w2 = (const float*)d_in[7];
    const float* mlp_b2 = (const float*)d_in[8];

    float* wt_qkv;  cudaGetSymbolAddress((void**)&wt_qkv,  g_wt_qkv);
    float* wt_proj; cudaGetSymbolAddress((void**)&wt_proj, g_wt_proj);
    float* qkv;     cudaGetSymbolAddress((void**)&qkv,     g_qkv);
    float* attn;    cudaGetSymbolAddress((void**)&attn,    g_attn);
    float* x32;     cudaGetSymbolAddress((void**)&x32,     g_x32);

    convert_x_kernel<<<(MTOT * CDIM / 4 + 255) / 256, 256>>>(x);
    transpose_kernel<<<dim3(3 * CDIM / 32, CDIM / 32), dim3(32, 8)>>>(qkv_w, wt_qkv, CDIM, 3 * CDIM);
    transpose_kernel<<<dim3(CDIM / 32, CDIM / 32), dim3(32, 8)>>>(proj_w, wt_proj, CDIM, CDIM);
    bias_kernel<<<16, 256>>>(mlp_w1, mlp_b1, mlp_w2, mlp_b2);

    cudaFuncSetAttribute(gemm_tf32<true>,  cudaFuncAttributeMaxDynamicSharedMemorySize, GEMM_SMEM);
    cudaFuncSetAttribute(gemm_tf32<false>, cudaFuncAttributeMaxDynamicSharedMemorySize, GEMM_SMEM);
    cudaFuncSetAttribute(attn_kernel, cudaFuncAttributeMaxDynamicSharedMemorySize, ATTN_SMEM);

    // QKV GEMM: [131072,384] @ [384,1152] -> tf32-rounded qkv
    gemm_tf32<true><<<dim3(9, MTOT / 128), 256, GEMM_SMEM>>>(x32, wt_qkv, qkv_b, qkv, 3 * CDIM);

    // attention (tensor cores, register softmax) -> tf32-rounded attn
    attn_kernel<<<NWIN, 256, ATTN_SMEM>>>();

    // projection GEMM: [131072,384] @ [384,384] -> d_out (fp32)
    gemm_tf32<false><<<dim3(3, MTOT / 128), 256, GEMM_SMEM>>>(attn, wt_proj, proj_b, (float*)d_out, CDIM);
}

// round 8
// speedup vs baseline: 1.1818x; 1.0792x over previous
#include <cuda_runtime.h>
#include <cstdint>
#include <math.h>

// Problem constants
#define NWIN 2048
#define NTOK 64
#define CDIM 384
#define NH   12
#define HD   32
#define MTOT (NWIN * NTOK)          // 131072 rows

// ---------------------------------------------------------------------------
// Device scratch
// ---------------------------------------------------------------------------
__device__ float g_x32[(size_t)MTOT * CDIM];           // x pre-rounded to tf32
__device__ float g_qkv[(size_t)MTOT * 3 * CDIM];       // [M,1152] tf32 bits
__device__ float g_attn[(size_t)MTOT * CDIM];          // [M,384]  tf32 bits
__device__ float g_bias[NH * NTOK * NTOK];             // fp32
__device__ float g_wt_qkv[(size_t)3 * CDIM * CDIM];    // [1152,384] K-major tf32
__device__ float g_wt_proj[(size_t)CDIM * CDIM];       // [384,384]  K-major tf32

__device__ __forceinline__ uint32_t f2tf32(float v) {
    uint32_t r;
    asm("cvt.rna.tf32.f32 %0, %1;" : "=r"(r) : "f"(v));
    return r;
}
__device__ __forceinline__ float f2tf32f(float v) { return __uint_as_float(f2tf32(v)); }

__device__ __forceinline__ void mma_tf32(float* d, const uint32_t* a, const uint32_t* b) {
    asm volatile(
        "mma.sync.aligned.m16n8k8.row.col.f32.tf32.tf32.f32 "
        "{%0,%1,%2,%3}, {%4,%5,%6,%7}, {%8,%9}, {%0,%1,%2,%3};"
        : "+f"(d[0]), "+f"(d[1]), "+f"(d[2]), "+f"(d[3])
        : "r"(a[0]), "r"(a[1]), "r"(a[2]), "r"(a[3]), "r"(b[0]), "r"(b[1]));
}
// ldmatrix x4 on fp32 data (b16 pairs == one f32): lane i of each 8x4 f32
// block receives element (row i>>2, col i&3) — exactly the mma tf32 fragment.
__device__ __forceinline__ void ldsm4(uint32_t* r, uint32_t addr) {
    asm volatile("ldmatrix.sync.aligned.m8n8.x4.shared.b16 {%0,%1,%2,%3}, [%4];"
                 : "=r"(r[0]), "=r"(r[1]), "=r"(r[2]), "=r"(r[3]) : "r"(addr));
}
__device__ __forceinline__ uint32_t smem_u32(const void* p) {
    uint32_t a;
    asm("{ .reg .u64 t; cvta.to.shared.u64 t, %1; cvt.u32.u64 %0, t; }" : "=r"(a) : "l"(p));
    return a;
}
__device__ __forceinline__ void cp16(uint32_t dst, const void* src) {
    asm volatile("cp.async.cg.shared.global [%0], [%1], 16;" :: "r"(dst), "l"(src));
}
#define CP_COMMIT() asm volatile("cp.async.commit_group;" ::: "memory")
#define CP_WAIT(N)  asm volatile("cp.async.wait_group %0;" :: "n"(N) : "memory")

// ---------------------------------------------------------------------------
// x -> tf32 pre-round
// ---------------------------------------------------------------------------
__global__ void convert_x_kernel(const float* __restrict__ in) {
    size_t i = ((size_t)blockIdx.x * blockDim.x + threadIdx.x) * 4;
    if (i >= (size_t)MTOT * CDIM) return;
    float4 v = *(const float4*)(in + i);
    float4 o;
    o.x = f2tf32f(v.x); o.y = f2tf32f(v.y); o.z = f2tf32f(v.z); o.w = f2tf32f(v.w);
    *(float4*)(g_x32 + i) = o;
}

// ---------------------------------------------------------------------------
// weight transpose + tf32 round:  out[N,K] = tf32(in[K,N])
// ---------------------------------------------------------------------------
__global__ void transpose_kernel(const float* __restrict__ in, float* __restrict__ out,
                                 int K, int N) {
    __shared__ float tl[32][33];
    int n0 = blockIdx.x * 32, k0 = blockIdx.y * 32;
    int x = threadIdx.x, y = threadIdx.y;
#pragma unroll
    for (int j = y; j < 32; j += 8) tl[j][x] = in[(size_t)(k0 + j) * N + n0 + x];
    __syncthreads();
#pragma unroll
    for (int j = y; j < 32; j += 8) out[(size_t)(n0 + j) * K + k0 + x] = f2tf32f(tl[x][j]);
}

// ---------------------------------------------------------------------------
// relative position bias table (fp32), weights staged in smem
// ---------------------------------------------------------------------------
__global__ void bias_kernel(const float* __restrict__ w1, const float* __restrict__ b1,
                            const float* __restrict__ w2, const float* __restrict__ b2) {
    __shared__ float sw1[192], sb1[64], sw2[768], sb2[12];
    int tid = threadIdx.x;
    if (tid < 192) sw1[tid] = w1[tid];
    if (tid < 64)  sb1[tid] = b1[tid];
    for (int i = tid; i < 768; i += blockDim.x) sw2[i] = w2[i];
    if (tid < 12)  sb2[tid] = b2[tid];
    __syncthreads();

    int idx = blockIdx.x * blockDim.x + tid;
    if (idx >= NTOK * NTOK) return;
    int n = idx / NTOK, m = idx % NTOK;
    float r0 = (float)((n >> 4) & 3) - (float)((m >> 4) & 3);
    float r1 = (float)((n >> 2) & 3) - (float)((m >> 2) & 3);
    float r2 = (float)(n & 3)        - (float)(m & 3);

    float outh[NH];
#pragma unroll
    for (int h = 0; h < NH; h++) outh[h] = sb2[h];
    for (int j = 0; j < 64; j++) {
        float hj = fmaf(r0, sw1[j], fmaf(r1, sw1[64 + j], fmaf(r2, sw1[128 + j], sb1[j])));
        hj = fmaxf(hj, 0.0f);
#pragma unroll
        for (int h = 0; h < NH; h++) outh[h] = fmaf(hj, sw2[j * NH + h], outh[h]);
    }
#pragma unroll
    for (int h = 0; h < NH; h++) g_bias[h * NTOK * NTOK + idx] = outh[h];
}

// ---------------------------------------------------------------------------
// tf32 mma.sync GEMM: CTA 128x128, 8 warps (2Mx4N), warp 64x32,
// 3-stage cp.async ring, ldmatrix fragment loads, zero CVT in mainloop.
// ---------------------------------------------------------------------------
#define KC 32
#define NCH (CDIM / KC)   // 12
#define GEMM_SMEM (24576 * 4)   // 96 KB

template <bool ROUND_OUT>
__global__ void __launch_bounds__(256, 2)
gemm_tf32(const float* __restrict__ A, const float* __restrict__ Bt,
          const float* __restrict__ bias, float* __restrict__ out, int ldc) {
    extern __shared__ float dsm[];

    const int t    = threadIdx.x;
    const int wid  = t >> 5, lane = t & 31;
    const int wm   = wid & 1;
    const int wn   = wid >> 1;
    const int n0   = blockIdx.x * 128;
    const int m0   = blockIdx.y * 128;
    const int lrow = lane >> 2;
    const int lcol = lane & 3;

    const uint32_t sbase = smem_u32(dsm);

    float acc[4][4][4];
#pragma unroll
    for (int i = 0; i < 4; i++)
#pragma unroll
        for (int j = 0; j < 4; j++)
#pragma unroll
            for (int r = 0; r < 4; r++) acc[i][j][r] = 0.0f;

    const int ldr = t >> 3;
    const int ldg = t & 7;

    // ldmatrix per-lane geometry
    const int grp = lane >> 3;       // x4 address group 0..3
    const int lr8 = lane & 7;        // row within 8-row block
    const int ahalf = grp >> 1;      // A: k-halfgroup selector
    const int apar  = grp & 1;       // A: +8-row selector
    const int bnt   = grp >> 1;      // B: nt-within-pair selector
    const int bk    = grp & 1;       // B: k-halfgroup selector

    uint32_t aoff[4]; int arl[4];
#pragma unroll
    for (int mt = 0; mt < 4; mt++) {
        int r = wm * 64 + mt * 16 + apar * 8 + lr8;
        aoff[mt] = (uint32_t)(r * 128);   // bytes (row stride 32 floats)
        arl[mt]  = r & 7;
    }
    uint32_t boff[2]; int brl[2];
#pragma unroll
    for (int p = 0; p < 2; p++) {
        int r = wn * 32 + (2 * p + bnt) * 8 + lr8;
        boff[p] = (uint32_t)(r * 128);
        brl[p]  = r & 7;
    }

#define ISSUE(ch, st) do {                                                              \
        int _k0 = (ch) * KC;                                                            \
        _Pragma("unroll")                                                               \
        for (int _i = 0; _i < 4; _i++) {                                                \
            int _row = ldr + _i * 32;                                                   \
            int _sg  = ldg ^ (_row & 7);                                                \
            uint32_t _off = (uint32_t)((st) * 16384 + (_row * 32 + _sg * 4) * 4);       \
            cp16(sbase + _off,         A  + (size_t)(m0 + _row) * CDIM + _k0 + ldg * 4); \
            cp16(sbase + 49152 + _off, Bt + (size_t)(n0 + _row) * CDIM + _k0 + ldg * 4); \
        }                                                                               \
        CP_COMMIT();                                                                    \
    } while (0)

#define COMPUTE(st) do {                                                                \
        const uint32_t Aab = sbase + (st) * 16384;                                      \
        const uint32_t Bab = sbase + 49152 + (st) * 16384;                              \
        _Pragma("unroll")                                                               \
        for (int ks = 0; ks < 4; ks++) {                                                \
            uint32_t afr[4][4], bfr[2][4];                                              \
            _Pragma("unroll")                                                           \
            for (int mt = 0; mt < 4; mt++)                                              \
                ldsm4(afr[mt], Aab + aoff[mt] +                                         \
                      (uint32_t)(((2 * ks + ahalf) ^ arl[mt]) << 4));                   \
            _Pragma("unroll")                                                           \
            for (int p = 0; p < 2; p++)                                                 \
                ldsm4(bfr[p], Bab + boff[p] +                                           \
                      (uint32_t)(((2 * ks + bk) ^ brl[p]) << 4));                       \
            _Pragma("unroll")                                                           \
            for (int mt = 0; mt < 4; mt++) {                                            \
                mma_tf32(acc[mt][0], afr[mt], &bfr[0][0]);                              \
                mma_tf32(acc[mt][1], afr[mt], &bfr[0][2]);                              \
                mma_tf32(acc[mt][2], afr[mt], &bfr[1][0]);                              \
                mma_tf32(acc[mt][3], afr[mt], &bfr[1][2]);                              \
            }                                                                           \
        }                                                                               \
    } while (0)

#define STEP(c, st, stnext) do {                                                        \
        if ((c) == NCH - 1) { CP_WAIT(0); } else { CP_WAIT(1); }                        \
        __syncthreads();                                                                \
        if ((c) + 2 < NCH) ISSUE((c) + 2, stnext);                                      \
        COMPUTE(st);                                                                    \
    } while (0)

    ISSUE(0, 0);
    ISSUE(1, 1);
#pragma unroll
    for (int c3 = 0; c3 < NCH; c3 += 3) {
        STEP(c3 + 0, 0, 2);
        STEP(c3 + 1, 1, 0);
        STEP(c3 + 2, 2, 1);
    }

#pragma unroll
    for (int mt = 0; mt < 4; mt++) {
#pragma unroll
        for (int nt = 0; nt < 4; nt++) {
            int row = m0 + wm * 64 + mt * 16 + lrow;
            int col = n0 + wn * 32 + nt * 8 + lcol * 2;
            float2 bv = *(const float2*)(bias + col);
            float2 o0, o1;
            if (ROUND_OUT) {
                o0.x = f2tf32f(acc[mt][nt][0] + bv.x); o0.y = f2tf32f(acc[mt][nt][1] + bv.y);
                o1.x = f2tf32f(acc[mt][nt][2] + bv.x); o1.y = f2tf32f(acc[mt][nt][3] + bv.y);
            } else {
                o0.x = acc[mt][nt][0] + bv.x; o0.y = acc[mt][nt][1] + bv.y;
                o1.x = acc[mt][nt][2] + bv.x; o1.y = acc[mt][nt][3] + bv.y;
            }
            *(float2*)(out + (size_t)row * ldc + col)       = o0;
            *(float2*)(out + (size_t)(row + 8) * ldc + col) = o1;
        }
    }
#undef STEP
#undef COMPUTE
#undef ISSUE
}

// ---------------------------------------------------------------------------
// Tensor-core attention: register softmax + shfl repack + ldmatrix loads.
// Block = 1 window, 256 thr = 2 teams x 4 warps; team does 6 heads.
// Team smem (floats): qs[64*36]=2304, ks[64*36]=2304, vt[32*68]=2176 = 6784
// ---------------------------------------------------------------------------
#define TEAM_F 6784
#define ATTN_SMEM (2 * TEAM_F * 4)   // 53 KB

__global__ void __launch_bounds__(256, 2)
attn_kernel() {
    extern __shared__ float dsm[];
    const int b    = blockIdx.x;
    const int t    = threadIdx.x;
    const int team = t >> 7;
    const int lt   = t & 127;
    const int w    = lt >> 5;
    const int lane = t & 31;
    const int lrow = lane >> 2;
    const int lcol = lane & 3;

    float* qs = dsm + team * TEAM_F;   // [64][36]
    float* ks = qs + 64 * 36;          // [64][36]
    float* vt = ks + 64 * 36;          // [32][68]  (d, m)

    const uint32_t qb = smem_u32(qs);
    const uint32_t kb = smem_u32(ks);
    const uint32_t vb = smem_u32(vt);

    const float scale = 0.17677669529663687f;  // 1/sqrt(32)
    const float* qkvb = g_qkv + (size_t)b * NTOK * (3 * CDIM);

    const int row0 = w * 16 + lrow;    // warp's S row (and +8)

    // ldmatrix geometry
    const int grp = lane >> 3, lr8 = lane & 7;
    const uint32_t qrowoff = (uint32_t)((w * 16 + (grp & 1) * 8 + lr8) * 144); // stride 36 fl
    const int qhalf = grp >> 1;
    const int bnt = grp >> 1, bk = grp & 1;
    uint32_t krowoff[4];
#pragma unroll
    for (int p = 0; p < 4; p++)
        krowoff[p] = (uint32_t)(((2 * p + bnt) * 8 + lr8) * 144);
    uint32_t vrowoff[2];
#pragma unroll
    for (int p = 0; p < 2; p++)
        vrowoff[p] = (uint32_t)(((2 * p + bnt) * 8 + lr8) * 272);               // stride 68 fl

    for (int hi = 0; hi < 6; hi++) {
        const int h = hi * 2 + team;
        const int qoff = h * HD, koff = CDIM + h * HD, voff = 2 * CDIM + h * HD;

        // load q,k row-major; v transposed
        for (int i = lt; i < 512; i += 128) {
            int n = i >> 3, c4 = i & 7;
            const float* rowp = qkvb + (size_t)n * (3 * CDIM);
            float4 qv = *(const float4*)(rowp + qoff + c4 * 4);
            float4 kv = *(const float4*)(rowp + koff + c4 * 4);
            float4 vv = *(const float4*)(rowp + voff + c4 * 4);
            float* qd = qs + n * 36 + c4 * 4;
            float* kd = ks + n * 36 + c4 * 4;
            qd[0] = qv.x; qd[1] = qv.y; qd[2] = qv.z; qd[3] = qv.w;
            kd[0] = kv.x; kd[1] = kv.y; kd[2] = kv.z; kd[3] = kv.w;
            int d0 = c4 * 4;
            vt[(d0 + 0) * 68 + n] = vv.x;
            vt[(d0 + 1) * 68 + n] = vv.y;
            vt[(d0 + 2) * 68 + n] = vv.z;
            vt[(d0 + 3) * 68 + n] = vv.w;
        }
        __syncthreads();

        // ---- S = Q K^T  (warp: rows row0/row0+8, all 64 cols)
        float sacc[8][4];
#pragma unroll
        for (int nt = 0; nt < 8; nt++)
#pragma unroll
            for (int r = 0; r < 4; r++) sacc[nt][r] = 0.0f;

#pragma unroll
        for (int kc = 0; kc < 4; kc++) {
            uint32_t af[4], bf[4][4];
            ldsm4(af, qb + qrowoff + (uint32_t)((2 * kc + qhalf) << 4));
#pragma unroll
            for (int p = 0; p < 4; p++)
                ldsm4(bf[p], kb + krowoff[p] + (uint32_t)((2 * kc + bk) << 4));
#pragma unroll
            for (int p = 0; p < 4; p++) {
                mma_tf32(sacc[2 * p],     af, &bf[p][0]);
                mma_tf32(sacc[2 * p + 1], af, &bf[p][2]);
            }
        }

        // ---- scale + bias (in registers)
        const float* bh = g_bias + h * NTOK * NTOK;
#pragma unroll
        for (int nt = 0; nt < 8; nt++) {
            int col = nt * 8 + lcol * 2;
            float2 b0 = *(const float2*)(bh + row0 * 64 + col);
            float2 b1 = *(const float2*)(bh + (row0 + 8) * 64 + col);
            sacc[nt][0] = fmaf(sacc[nt][0], scale, b0.x);
            sacc[nt][1] = fmaf(sacc[nt][1], scale, b0.y);
            sacc[nt][2] = fmaf(sacc[nt][2], scale, b1.x);
            sacc[nt][3] = fmaf(sacc[nt][3], scale, b1.y);
        }

        // ---- register softmax
        {
            float mx0 = -1e30f, mx1 = -1e30f;
#pragma unroll
            for (int nt = 0; nt < 8; nt++) {
                mx0 = fmaxf(mx0, fmaxf(sacc[nt][0], sacc[nt][1]));
                mx1 = fmaxf(mx1, fmaxf(sacc[nt][2], sacc[nt][3]));
            }
            mx0 = fmaxf(mx0, __shfl_xor_sync(0xFFFFFFFFu, mx0, 1));
            mx0 = fmaxf(mx0, __shfl_xor_sync(0xFFFFFFFFu, mx0, 2));
            mx1 = fmaxf(mx1, __shfl_xor_sync(0xFFFFFFFFu, mx1, 1));
            mx1 = fmaxf(mx1, __shfl_xor_sync(0xFFFFFFFFu, mx1, 2));
            float s0 = 0.0f, s1 = 0.0f;
#pragma unroll
            for (int nt = 0; nt < 8; nt++) {
                sacc[nt][0] = __expf(sacc[nt][0] - mx0); s0 += sacc[nt][0];
                sacc[nt][1] = __expf(sacc[nt][1] - mx0); s0 += sacc[nt][1];
                sacc[nt][2] = __expf(sacc[nt][2] - mx1); s1 += sacc[nt][2];
                sacc[nt][3] = __expf(sacc[nt][3] - mx1); s1 += sacc[nt][3];
            }
            s0 += __shfl_xor_sync(0xFFFFFFFFu, s0, 1);
            s0 += __shfl_xor_sync(0xFFFFFFFFu, s0, 2);
            s1 += __shfl_xor_sync(0xFFFFFFFFu, s1, 1);
            s1 += __shfl_xor_sync(0xFFFFFFFFu, s1, 2);
            float i0 = 1.0f / s0, i1 = 1.0f / s1;
#pragma unroll
            for (int nt = 0; nt < 8; nt++) {
                sacc[nt][0] *= i0; sacc[nt][1] *= i0;
                sacc[nt][2] *= i1; sacc[nt][3] *= i1;
            }
        }

        // cvt P to tf32 bits (accumulator layout)
        uint32_t pc[8][4];
#pragma unroll
        for (int nt = 0; nt < 8; nt++)
#pragma unroll
            for (int r = 0; r < 4; r++) pc[nt][r] = f2tf32(sacc[nt][r]);

        // ---- repack accumulator-layout P -> A-fragments via shfl
        const int src  = lrow * 4 + (lcol >> 1);
        const int src2 = src + 2;
        const int par  = lcol & 1;
        uint32_t pf[8][4];
#pragma unroll
        for (int kc = 0; kc < 8; kc++) {
            uint32_t x0 = __shfl_sync(0xFFFFFFFFu, pc[kc][0], src);
            uint32_t x1 = __shfl_sync(0xFFFFFFFFu, pc[kc][1], src);
            uint32_t x2 = __shfl_sync(0xFFFFFFFFu, pc[kc][2], src);
            uint32_t x3 = __shfl_sync(0xFFFFFFFFu, pc[kc][3], src);
            uint32_t y0 = __shfl_sync(0xFFFFFFFFu, pc[kc][0], src2);
            uint32_t y1 = __shfl_sync(0xFFFFFFFFu, pc[kc][1], src2);
            uint32_t y2 = __shfl_sync(0xFFFFFFFFu, pc[kc][2], src2);
            uint32_t y3 = __shfl_sync(0xFFFFFFFFu, pc[kc][3], src2);
            pf[kc][0] = par ? x1 : x0;
            pf[kc][1] = par ? x3 : x2;
            pf[kc][2] = par ? y1 : y0;
            pf[kc][3] = par ? y3 : y2;
        }

        // ---- O = P V
        float oacc[4][4];
#pragma unroll
        for (int nt = 0; nt < 4; nt++)
#pragma unroll
            for (int r = 0; r < 4; r++) oacc[nt][r] = 0.0f;

#pragma unroll
        for (int kc = 0; kc < 8; kc++) {
            uint32_t vf[2][4];
#pragma unroll
            for (int p = 0; p < 2; p++)
                ldsm4(vf[p], vb + vrowoff[p] + (uint32_t)((2 * kc + bk) << 4));
            mma_tf32(oacc[0], pf[kc], &vf[0][0]);
            mma_tf32(oacc[1], pf[kc], &vf[0][2]);
            mma_tf32(oacc[2], pf[kc], &vf[1][0]);
            mma_tf32(oacc[3], pf[kc], &vf[1][2]);
        }
        {
            float* og = g_attn + (size_t)b * NTOK * CDIM + h * HD;
#pragma unroll
            for (int nt = 0; nt < 4; nt++) {
                int col = nt * 8 + lcol * 2;
                float2 o0 = make_float2(f2tf32f(oacc[nt][0]), f2tf32f(oacc[nt][1]));
                float2 o1 = make_float2(f2tf32f(oacc[nt][2]), f2tf32f(oacc[nt][3]));
                *(float2*)(og + (size_t)row0 * CDIM + col)       = o0;
                *(float2*)(og + (size_t)(row0 + 8) * CDIM + col) = o1;
            }
        }
        __syncthreads();
    }
}

// ---------------------------------------------------------------------------
extern "C" void kernel_launch(void* const* d_in, const int* in_sizes, int n_in,
                              void* d_out, int out_size) {
    const float* x      = (const float*)d_in[0];
    const float* qkv_w  = (const float*)d_in[1];
    const float* qkv_b  = (const float*)d_in[2];
    const float* proj_w = (const float*)d_in[3];
    const float* proj_b = (const float*)d_in[4];
    const float* mlp_w1 = (const float*)d_in[5];
    const float* mlp_b1 = (const float*)d_in[6];
    const float* mlp_w2 = (const float*)d_in[7];
    const float* mlp_b2 = (const float*)d_in[8];

    float* wt_qkv;  cudaGetSymbolAddress((void**)&wt_qkv,  g_wt_qkv);
    float* wt_proj; cudaGetSymbolAddress((void**)&wt_proj, g_wt_proj);
    float* qkv;     cudaGetSymbolAddress((void**)&qkv,     g_qkv);
    float* attn;    cudaGetSymbolAddress((void**)&attn,    g_attn);
    float* x32;     cudaGetSymbolAddress((void**)&x32,     g_x32);

    convert_x_kernel<<<(MTOT * CDIM / 4 + 255) / 256, 256>>>(x);
    transpose_kernel<<<dim3(3 * CDIM / 32, CDIM / 32), dim3(32, 8)>>>(qkv_w, wt_qkv, CDIM, 3 * CDIM);
    transpose_kernel<<<dim3(CDIM / 32, CDIM / 32), dim3(32, 8)>>>(proj_w, wt_proj, CDIM, CDIM);
    bias_kernel<<<16, 256>>>(mlp_w1, mlp_b1, mlp_w2, mlp_b2);

    cudaFuncSetAttribute(gemm_tf32<true>,  cudaFuncAttributeMaxDynamicSharedMemorySize, GEMM_SMEM);
    cudaFuncSetAttribute(gemm_tf32<false>, cudaFuncAttributeMaxDynamicSharedMemorySize, GEMM_SMEM);
    cudaFuncSetAttribute(attn_kernel, cudaFuncAttributeMaxDynamicSharedMemorySize, ATTN_SMEM);

    // QKV GEMM: [131072,384] @ [384,1152] -> tf32-rounded qkv
    gemm_tf32<true><<<dim3(9, MTOT / 128), 256, GEMM_SMEM>>>(x32, wt_qkv, qkv_b, qkv, 3 * CDIM);

    // attention (tensor cores, register softmax, ldmatrix) -> tf32-rounded attn
    attn_kernel<<<NWIN, 256, ATTN_SMEM>>>();

    // projection GEMM: [131072,384] @ [384,384] -> d_out (fp32)
    gemm_tf32<false><<<dim3(3, MTOT / 128), 256, GEMM_SMEM>>>(attn, wt_proj, proj_b, (float*)d_out, CDIM);
}

// round 9
// speedup vs baseline: 1.4013x; 1.1857x over previous
#include <cuda_runtime.h>
#include <cstdint>
#include <math.h>

// Problem constants
#define NWIN 2048
#define NTOK 64
#define CDIM 384
#define NH   12
#define HD   32
#define MTOT (NWIN * NTOK)          // 131072 rows

// ---------------------------------------------------------------------------
// Device scratch
// ---------------------------------------------------------------------------
__device__ float g_x32[(size_t)MTOT * CDIM];           // x pre-rounded to tf32
__device__ float g_attn[(size_t)MTOT * CDIM];          // [M,384]  tf32 bits
__device__ float g_bias[NH * NTOK * NTOK];             // fp32
__device__ float g_wt_qkv2[(size_t)NH * 96 * CDIM];    // head-grouped [h][qkv 96][384]
__device__ float g_wt_proj[(size_t)CDIM * CDIM];       // [384,384]  K-major tf32

__device__ __forceinline__ uint32_t f2tf32(float v) {
    uint32_t r;
    asm("cvt.rna.tf32.f32 %0, %1;" : "=r"(r) : "f"(v));
    return r;
}
__device__ __forceinline__ float f2tf32f(float v) { return __uint_as_float(f2tf32(v)); }

__device__ __forceinline__ void mma_tf32(float* d, const uint32_t* a, const uint32_t* b) {
    asm volatile(
        "mma.sync.aligned.m16n8k8.row.col.f32.tf32.tf32.f32 "
        "{%0,%1,%2,%3}, {%4,%5,%6,%7}, {%8,%9}, {%0,%1,%2,%3};"
        : "+f"(d[0]), "+f"(d[1]), "+f"(d[2]), "+f"(d[3])
        : "r"(a[0]), "r"(a[1]), "r"(a[2]), "r"(a[3]), "r"(b[0]), "r"(b[1]));
}
__device__ __forceinline__ void ldsm4(uint32_t* r, uint32_t addr) {
    asm volatile("ldmatrix.sync.aligned.m8n8.x4.shared.b16 {%0,%1,%2,%3}, [%4];"
                 : "=r"(r[0]), "=r"(r[1]), "=r"(r[2]), "=r"(r[3]) : "r"(addr));
}
__device__ __forceinline__ uint32_t smem_u32(const void* p) {
    uint32_t a;
    asm("{ .reg .u64 t; cvta.to.shared.u64 t, %1; cvt.u32.u64 %0, t; }" : "=r"(a) : "l"(p));
    return a;
}
__device__ __forceinline__ void cp16(uint32_t dst, const void* src) {
    asm volatile("cp.async.cg.shared.global [%0], [%1], 16;" :: "r"(dst), "l"(src));
}
#define CP_COMMIT() asm volatile("cp.async.commit_group;" ::: "memory")
#define CP_WAIT(N)  asm volatile("cp.async.wait_group %0;" :: "n"(N) : "memory")

// ---------------------------------------------------------------------------
// x -> tf32 pre-round
// ---------------------------------------------------------------------------
__global__ void convert_x_kernel(const float* __restrict__ in) {
    size_t i = ((size_t)blockIdx.x * blockDim.x + threadIdx.x) * 4;
    if (i >= (size_t)MTOT * CDIM) return;
    float4 v = *(const float4*)(in + i);
    float4 o;
    o.x = f2tf32f(v.x); o.y = f2tf32f(v.y); o.z = f2tf32f(v.z); o.w = f2tf32f(v.w);
    *(float4*)(g_x32 + i) = o;
}

// ---------------------------------------------------------------------------
// proj weight transpose + tf32 round:  out[N,K] = tf32(in[K,N])
// ---------------------------------------------------------------------------
__global__ void transpose_kernel(const float* __restrict__ in, float* __restrict__ out,
                                 int K, int N) {
    __shared__ float tl[32][33];
    int n0 = blockIdx.x * 32, k0 = blockIdx.y * 32;
    int x = threadIdx.x, y = threadIdx.y;
#pragma unroll
    for (int j = y; j < 32; j += 8) tl[j][x] = in[(size_t)(k0 + j) * N + n0 + x];
    __syncthreads();
#pragma unroll
    for (int j = y; j < 32; j += 8) out[(size_t)(n0 + j) * K + k0 + x] = f2tf32f(tl[x][j]);
}

// ---------------------------------------------------------------------------
// qkv weight transpose to head-grouped K-major:
// out[(h*96 + part*32 + c)][k] = tf32(in[k][part*384 + h*32 + c])
// ---------------------------------------------------------------------------
__global__ void transpose_qkv_kernel(const float* __restrict__ in) {
    __shared__ float tl[32][33];
    int n0 = blockIdx.x * 32;   // source col block; part/head constant per block
    int k0 = blockIdx.y * 32;
    int x = threadIdx.x, y = threadIdx.y;
#pragma unroll
    for (int j = y; j < 32; j += 8) tl[j][x] = in[(size_t)(k0 + j) * (3 * CDIM) + n0 + x];
    __syncthreads();
    int part = n0 / CDIM;
    int h    = (n0 % CDIM) / 32;
    int rbase = h * 96 + part * 32;
#pragma unroll
    for (int j = y; j < 32; j += 8)
        g_wt_qkv2[(size_t)(rbase + j) * CDIM + k0 + x] = f2tf32f(tl[x][j]);
}

// ---------------------------------------------------------------------------
// relative position bias table (fp32), weights staged in smem
// ---------------------------------------------------------------------------
__global__ void bias_kernel(const float* __restrict__ w1, const float* __restrict__ b1,
                            const float* __restrict__ w2, const float* __restrict__ b2) {
    __shared__ float sw1[192], sb1[64], sw2[768], sb2[12];
    int tid = threadIdx.x;
    if (tid < 192) sw1[tid] = w1[tid];
    if (tid < 64)  sb1[tid] = b1[tid];
    for (int i = tid; i < 768; i += blockDim.x) sw2[i] = w2[i];
    if (tid < 12)  sb2[tid] = b2[tid];
    __syncthreads();

    int idx = blockIdx.x * blockDim.x + tid;
    if (idx >= NTOK * NTOK) return;
    int n = idx / NTOK, m = idx % NTOK;
    float r0 = (float)((n >> 4) & 3) - (float)((m >> 4) & 3);
    float r1 = (float)((n >> 2) & 3) - (float)((m >> 2) & 3);
    float r2 = (float)(n & 3)        - (float)(m & 3);

    float outh[NH];
#pragma unroll
    for (int h = 0; h < NH; h++) outh[h] = sb2[h];
    for (int j = 0; j < 64; j++) {
        float hj = fmaf(r0, sw1[j], fmaf(r1, sw1[64 + j], fmaf(r2, sw1[128 + j], sb1[j])));
        hj = fmaxf(hj, 0.0f);
#pragma unroll
        for (int h = 0; h < NH; h++) outh[h] = fmaf(hj, sw2[j * NH + h], outh[h]);
    }
#pragma unroll
    for (int h = 0; h < NH; h++) g_bias[h * NTOK * NTOK + idx] = outh[h];
}

// ---------------------------------------------------------------------------
// FUSED QKV-GEMM + attention. Grid (12 heads, 1024 row-blocks), 256 threads.
// GEMM: M=128 (2 windows) x N=96 (head's q|k|v) x K=384. 8 warps 4Mx2N,
// warp 32x48, 3-stage cp.async + ldmatrix. Epilogue stages q/k/v into smem,
// then 2 teams x 4 warps run register-softmax attention per window.
// smem: A 3x16KB @0, B 3x12KB @49152 -> 86016 B. Attn staging reuses A/B:
//   qs[128][36] @0, ks[128][36] @4608fl, vt 2x[32][68] @9216fl (13568 fl)
// ---------------------------------------------------------------------------
#define NCH (CDIM / 32)          // 12
#define FUSED_SMEM 86016

__global__ void __launch_bounds__(256, 2)
qkv_attn_kernel(const float* __restrict__ A, const float* __restrict__ qkv_b) {
    extern __shared__ float dsm[];

    const int t    = threadIdx.x;
    const int wid  = t >> 5, lane = t & 31;
    const int wm   = wid & 3;          // 0..3 (32-row slab)
    const int wn   = wid >> 2;         // 0..1 (48-col slab)
    const int h    = blockIdx.x;
    const int m0   = blockIdx.y * 128;
    const int lrow = lane >> 2;
    const int lcol = lane & 3;

    const uint32_t sbase = smem_u32(dsm);
    const float* Bt = g_wt_qkv2 + (size_t)h * 96 * CDIM;

    float acc[2][6][4];
#pragma unroll
    for (int i = 0; i < 2; i++)
#pragma unroll
        for (int j = 0; j < 6; j++)
#pragma unroll
            for (int r = 0; r < 4; r++) acc[i][j][r] = 0.0f;

    const int ldr = t >> 3;            // 0..31
    const int ldg = t & 7;

    // ldmatrix geometry
    const int grp = lane >> 3, lr8 = lane & 7;
    const int ahalf = grp >> 1, apar = grp & 1;
    const int bnt = grp >> 1, bk = grp & 1;
    uint32_t aoff[2]; int arl[2];
#pragma unroll
    for (int mt = 0; mt < 2; mt++) {
        int r = wm * 32 + mt * 16 + apar * 8 + lr8;
        aoff[mt] = (uint32_t)(r * 128);
        arl[mt]  = r & 7;
    }
    uint32_t boff[3]; int brl[3];
#pragma unroll
    for (int p = 0; p < 3; p++) {
        int r = wn * 48 + (2 * p + bnt) * 8 + lr8;
        boff[p] = (uint32_t)(r * 128);
        brl[p]  = r & 7;
    }

#define ISSUE(ch, st) do {                                                              \
        int _k0 = (ch) * 32;                                                            \
        _Pragma("unroll")                                                               \
        for (int _i = 0; _i < 4; _i++) {                                                \
            int _row = ldr + _i * 32;                                                   \
            int _sg  = ldg ^ (_row & 7);                                                \
            cp16(sbase + (st) * 16384 + (uint32_t)((_row * 32 + _sg * 4) * 4),          \
                 A + (size_t)(m0 + _row) * CDIM + _k0 + ldg * 4);                       \
        }                                                                               \
        _Pragma("unroll")                                                               \
        for (int _i = 0; _i < 3; _i++) {                                                \
            int _row = ldr + _i * 32;                                                   \
            int _sg  = ldg ^ (_row & 7);                                                \
            cp16(sbase + 49152 + (st) * 12288 + (uint32_t)((_row * 32 + _sg * 4) * 4),  \
                 Bt + (size_t)_row * CDIM + _k0 + ldg * 4);                             \
        }                                                                               \
        CP_COMMIT();                                                                    \
    } while (0)

#define COMPUTE(st) do {                                                                \
        const uint32_t Aab = sbase + (st) * 16384;                                      \
        const uint32_t Bab = sbase + 49152 + (st) * 12288;                              \
        _Pragma("unroll")                                                               \
        for (int ks = 0; ks < 4; ks++) {                                                \
            uint32_t afr[2][4], bfr[3][4];                                              \
            _Pragma("unroll")                                                           \
            for (int mt = 0; mt < 2; mt++)                                              \
                ldsm4(afr[mt], Aab + aoff[mt] +                                         \
                      (uint32_t)(((2 * ks + ahalf) ^ arl[mt]) << 4));                   \
            _Pragma("unroll")                                                           \
            for (int p = 0; p < 3; p++)                                                 \
                ldsm4(bfr[p], Bab + boff[p] +                                           \
                      (uint32_t)(((2 * ks + bk) ^ brl[p]) << 4));                       \
            _Pragma("unroll")                                                           \
            for (int mt = 0; mt < 2; mt++) {                                            \
                _Pragma("unroll")                                                       \
                for (int p = 0; p < 3; p++) {                                           \
                    mma_tf32(acc[mt][2 * p],     afr[mt], &bfr[p][0]);                  \
                    mma_tf32(acc[mt][2 * p + 1], afr[mt], &bfr[p][2]);                  \
                }                                                                       \
            }                                                                           \
        }                                                                               \
    } while (0)

#define STEP(c, st, stnext) do {                                                        \
        if ((c) == NCH - 1) { CP_WAIT(0); } else { CP_WAIT(1); }                        \
        __syncthreads();                                                                \
        if ((c) + 2 < NCH) ISSUE((c) + 2, stnext);                                      \
        COMPUTE(st);                                                                    \
    } while (0)

    ISSUE(0, 0);
    ISSUE(1, 1);
#pragma unroll
    for (int c3 = 0; c3 < NCH; c3 += 3) {
        STEP(c3 + 0, 0, 2);
        STEP(c3 + 1, 1, 0);
        STEP(c3 + 2, 2, 1);
    }

    // ---- epilogue: stage q/k/v (+bias, tf32) into smem union
    float* qs  = dsm;                 // [128][36]
    float* ks_ = dsm + 4608;          // [128][36]
    float* vts = dsm + 9216;          // 2 x [32][68]
    __syncthreads();
#pragma unroll
    for (int mt = 0; mt < 2; mt++) {
#pragma unroll
        for (int nt = 0; nt < 6; nt++) {
            int row = wm * 32 + mt * 16 + lrow;
            int col = wn * 48 + nt * 8 + lcol * 2;
            int part = col >> 5, c = col & 31;
            float2 bv = *(const float2*)(qkv_b + part * CDIM + h * HD + c);
            float v00 = f2tf32f(acc[mt][nt][0] + bv.x);
            float v01 = f2tf32f(acc[mt][nt][1] + bv.y);
            float v10 = f2tf32f(acc[mt][nt][2] + bv.x);
            float v11 = f2tf32f(acc[mt][nt][3] + bv.y);
            if (part == 0) {
                qs[row * 36 + c] = v00; qs[row * 36 + c + 1] = v01;
                qs[(row + 8) * 36 + c] = v10; qs[(row + 8) * 36 + c + 1] = v11;
            } else if (part == 1) {
                ks_[row * 36 + c] = v00; ks_[row * 36 + c + 1] = v01;
                ks_[(row + 8) * 36 + c] = v10; ks_[(row + 8) * 36 + c + 1] = v11;
            } else {
                float* vb_ = vts + (row >> 6) * 2176;
                int mrow = row & 63;
                vb_[c * 68 + mrow] = v00;       vb_[(c + 1) * 68 + mrow] = v01;
                vb_[c * 68 + mrow + 8] = v10;   vb_[(c + 1) * 68 + mrow + 8] = v11;
            }
        }
    }
    __syncthreads();

    // ---- attention: team (wid>>2) = window, w = warp in team
    const int team = wid >> 2;
    const int w    = wid & 3;
    const float* qsw = qs  + team * 2304;
    const float* ksw = ks_ + team * 2304;
    const uint32_t qb = smem_u32(qsw);
    const uint32_t kb = smem_u32(ksw);
    const uint32_t vb = smem_u32(vts + team * 2176);

    const float scale = 0.17677669529663687f;
    const int row0 = w * 16 + lrow;

    const uint32_t qrowoff = (uint32_t)((w * 16 + (grp & 1) * 8 + lr8) * 144);
    const int qhalf = grp >> 1;
    uint32_t krowoff[4];
#pragma unroll
    for (int p = 0; p < 4; p++)
        krowoff[p] = (uint32_t)(((2 * p + bnt) * 8 + lr8) * 144);
    uint32_t vrowoff[2];
#pragma unroll
    for (int p = 0; p < 2; p++)
        vrowoff[p] = (uint32_t)(((2 * p + bnt) * 8 + lr8) * 272);

    // S = Q K^T
    float sacc[8][4];
#pragma unroll
    for (int nt = 0; nt < 8; nt++)
#pragma unroll
        for (int r = 0; r < 4; r++) sacc[nt][r] = 0.0f;

#pragma unroll
    for (int kc = 0; kc < 4; kc++) {
        uint32_t af[4], bf[4][4];
        ldsm4(af, qb + qrowoff + (uint32_t)((2 * kc + qhalf) << 4));
#pragma unroll
        for (int p = 0; p < 4; p++)
            ldsm4(bf[p], kb + krowoff[p] + (uint32_t)((2 * kc + bk) << 4));
#pragma unroll
        for (int p = 0; p < 4; p++) {
            mma_tf32(sacc[2 * p],     af, &bf[p][0]);
            mma_tf32(sacc[2 * p + 1], af, &bf[p][2]);
        }
    }

    // scale + bias
    const float* bh = g_bias + h * NTOK * NTOK;
#pragma unroll
    for (int nt = 0; nt < 8; nt++) {
        int col = nt * 8 + lcol * 2;
        float2 b0 = *(const float2*)(bh + row0 * 64 + col);
        float2 b1 = *(const float2*)(bh + (row0 + 8) * 64 + col);
        sacc[nt][0] = fmaf(sacc[nt][0], scale, b0.x);
        sacc[nt][1] = fmaf(sacc[nt][1], scale, b0.y);
        sacc[nt][2] = fmaf(sacc[nt][2], scale, b1.x);
        sacc[nt][3] = fmaf(sacc[nt][3], scale, b1.y);
    }

    // register softmax
    {
        float mx0 = -1e30f, mx1 = -1e30f;
#pragma unroll
        for (int nt = 0; nt < 8; nt++) {
            mx0 = fmaxf(mx0, fmaxf(sacc[nt][0], sacc[nt][1]));
            mx1 = fmaxf(mx1, fmaxf(sacc[nt][2], sacc[nt][3]));
        }
        mx0 = fmaxf(mx0, __shfl_xor_sync(0xFFFFFFFFu, mx0, 1));
        mx0 = fmaxf(mx0, __shfl_xor_sync(0xFFFFFFFFu, mx0, 2));
        mx1 = fmaxf(mx1, __shfl_xor_sync(0xFFFFFFFFu, mx1, 1));
        mx1 = fmaxf(mx1, __shfl_xor_sync(0xFFFFFFFFu, mx1, 2));
        float s0 = 0.0f, s1 = 0.0f;
#pragma unroll
        for (int nt = 0; nt < 8; nt++) {
            sacc[nt][0] = __expf(sacc[nt][0] - mx0); s0 += sacc[nt][0];
            sacc[nt][1] = __expf(sacc[nt][1] - mx0); s0 += sacc[nt][1];
            sacc[nt][2] = __expf(sacc[nt][2] - mx1); s1 += sacc[nt][2];
            sacc[nt][3] = __expf(sacc[nt][3] - mx1); s1 += sacc[nt][3];
        }
        s0 += __shfl_xor_sync(0xFFFFFFFFu, s0, 1);
        s0 += __shfl_xor_sync(0xFFFFFFFFu, s0, 2);
        s1 += __shfl_xor_sync(0xFFFFFFFFu, s1, 1);
        s1 += __shfl_xor_sync(0xFFFFFFFFu, s1, 2);
        float i0 = 1.0f / s0, i1 = 1.0f / s1;
#pragma unroll
        for (int nt = 0; nt < 8; nt++) {
            sacc[nt][0] *= i0; sacc[nt][1] *= i0;
            sacc[nt][2] *= i1; sacc[nt][3] *= i1;
        }
    }

    // cvt + shfl repack to A-fragments
    uint32_t pc[8][4];
#pragma unroll
    for (int nt = 0; nt < 8; nt++)
#pragma unroll
        for (int r = 0; r < 4; r++) pc[nt][r] = f2tf32(sacc[nt][r]);

    const int src  = lrow * 4 + (lcol >> 1);
    const int src2 = src + 2;
    const int par  = lcol & 1;
    uint32_t pf[8][4];
#pragma unroll
    for (int kc = 0; kc < 8; kc++) {
        uint32_t x0 = __shfl_sync(0xFFFFFFFFu, pc[kc][0], src);
        uint32_t x1 = __shfl_sync(0xFFFFFFFFu, pc[kc][1], src);
        uint32_t x2 = __shfl_sync(0xFFFFFFFFu, pc[kc][2], src);
        uint32_t x3 = __shfl_sync(0xFFFFFFFFu, pc[kc][3], src);
        uint32_t y0 = __shfl_sync(0xFFFFFFFFu, pc[kc][0], src2);
        uint32_t y1 = __shfl_sync(0xFFFFFFFFu, pc[kc][1], src2);
        uint32_t y2 = __shfl_sync(0xFFFFFFFFu, pc[kc][2], src2);
        uint32_t y3 = __shfl_sync(0xFFFFFFFFu, pc[kc][3], src2);
        pf[kc][0] = par ? x1 : x0;
        pf[kc][1] = par ? x3 : x2;
        pf[kc][2] = par ? y1 : y0;
        pf[kc][3] = par ? y3 : y2;
    }

    // O = P V
    float oacc[4][4];
#pragma unroll
    for (int nt = 0; nt < 4; nt++)
#pragma unroll
        for (int r = 0; r < 4; r++) oacc[nt][r] = 0.0f;

#pragma unroll
    for (int kc = 0; kc < 8; kc++) {
        uint32_t vf[2][4];
#pragma unroll
        for (int p = 0; p < 2; p++)
            ldsm4(vf[p], vb + vrowoff[p] + (uint32_t)((2 * kc + bk) << 4));
        mma_tf32(oacc[0], pf[kc], &vf[0][0]);
        mma_tf32(oacc[1], pf[kc], &vf[0][2]);
        mma_tf32(oacc[2], pf[kc], &vf[1][0]);
        mma_tf32(oacc[3], pf[kc], &vf[1][2]);
    }
    {
        float* og = g_attn + (size_t)(m0 + team * 64) * CDIM + h * HD;
#pragma unroll
        for (int nt = 0; nt < 4; nt++) {
            int col = nt * 8 + lcol * 2;
            float2 o0 = make_float2(f2tf32f(oacc[nt][0]), f2tf32f(oacc[nt][1]));
            float2 o1 = make_float2(f2tf32f(oacc[nt][2]), f2tf32f(oacc[nt][3]));
            *(float2*)(og + (size_t)row0 * CDIM + col)       = o0;
            *(float2*)(og + (size_t)(row0 + 8) * CDIM + col) = o1;
        }
    }
#undef STEP
#undef COMPUTE
#undef ISSUE
}

// ---------------------------------------------------------------------------
// proj GEMM (unchanged, proven): CTA 128x128, 8 warps 2Mx4N, warp 64x32,
// 3-stage cp.async + ldmatrix.
// ---------------------------------------------------------------------------
#define GEMM_SMEM (24576 * 4)   // 96 KB

__global__ void __launch_bounds__(256, 2)
gemm_tf32(const float* __restrict__ A, const float* __restrict__ Bt,
          const float* __restrict__ bias, float* __restrict__ out, int ldc) {
    extern __shared__ float dsm[];

    const int t    = threadIdx.x;
    const int wid  = t >> 5, lane = t & 31;
    const int wm   = wid & 1;
    const int wn   = wid >> 1;
    const int n0   = blockIdx.x * 128;
    const int m0   = blockIdx.y * 128;
    const int lrow = lane >> 2;
    const int lcol = lane & 3;

    const uint32_t sbase = smem_u32(dsm);

    float acc[4][4][4];
#pragma unroll
    for (int i = 0; i < 4; i++)
#pragma unroll
        for (int j = 0; j < 4; j++)
#pragma unroll
            for (int r = 0; r < 4; r++) acc[i][j][r] = 0.0f;

    const int ldr = t >> 3;
    const int ldg = t & 7;

    const int grp = lane >> 3, lr8 = lane & 7;
    const int ahalf = grp >> 1, apar = grp & 1;
    const int bnt = grp >> 1, bk = grp & 1;

    uint32_t aoff[4]; int arl[4];
#pragma unroll
    for (int mt = 0; mt < 4; mt++) {
        int r = wm * 64 + mt * 16 + apar * 8 + lr8;
        aoff[mt] = (uint32_t)(r * 128);
        arl[mt]  = r & 7;
    }
    uint32_t boff[2]; int brl[2];
#pragma unroll
    for (int p = 0; p < 2; p++) {
        int r = wn * 32 + (2 * p + bnt) * 8 + lr8;
        boff[p] = (uint32_t)(r * 128);
        brl[p]  = r & 7;
    }

#define ISSUE(ch, st) do {                                                              \
        int _k0 = (ch) * 32;                                                            \
        _Pragma("unroll")                                                               \
        for (int _i = 0; _i < 4; _i++) {                                                \
            int _row = ldr + _i * 32;                                                   \
            int _sg  = ldg ^ (_row & 7);                                                \
            uint32_t _off = (uint32_t)((st) * 16384 + (_row * 32 + _sg * 4) * 4);       \
            cp16(sbase + _off,         A  + (size_t)(m0 + _row) * CDIM + _k0 + ldg * 4); \
            cp16(sbase + 49152 + _off, Bt + (size_t)(n0 + _row) * CDIM + _k0 + ldg * 4); \
        }                                                                               \
        CP_COMMIT();                                                                    \
    } while (0)

#define COMPUTE(st) do {                                                                \
        const uint32_t Aab = sbase + (st) * 16384;                                      \
        const uint32_t Bab = sbase + 49152 + (st) * 16384;                              \
        _Pragma("unroll")                                                               \
        for (int ks = 0; ks < 4; ks++) {                                                \
            uint32_t afr[4][4], bfr[2][4];                                              \
            _Pragma("unroll")                                                           \
            for (int mt = 0; mt < 4; mt++)                                              \
                ldsm4(afr[mt], Aab + aoff[mt] +                                         \
                      (uint32_t)(((2 * ks + ahalf) ^ arl[mt]) << 4));                   \
            _Pragma("unroll")                                                           \
            for (int p = 0; p < 2; p++)                                                 \
                ldsm4(bfr[p], Bab + boff[p] +                                           \
                      (uint32_t)(((2 * ks + bk) ^ brl[p]) << 4));                       \
            _Pragma("unroll")                                                           \
            for (int mt = 0; mt < 4; mt++) {                                            \
                mma_tf32(acc[mt][0], afr[mt], &bfr[0][0]);                              \
                mma_tf32(acc[mt][1], afr[mt], &bfr[0][2]);                              \
                mma_tf32(acc[mt][2], afr[mt], &bfr[1][0]);                              \
                mma_tf32(acc[mt][3], afr[mt], &bfr[1][2]);                              \
            }                                                                           \
        }                                                                               \
    } while (0)

#define STEP(c, st, stnext) do {                                                        \
        if ((c) == NCH - 1) { CP_WAIT(0); } else { CP_WAIT(1); }                        \
        __syncthreads();                                                                \
        if ((c) + 2 < NCH) ISSUE((c) + 2, stnext);                                      \
        COMPUTE(st);                                                                    \
    } while (0)

    ISSUE(0, 0);
    ISSUE(1, 1);
#pragma unroll
    for (int c3 = 0; c3 < NCH; c3 += 3) {
        STEP(c3 + 0, 0, 2);
        STEP(c3 + 1, 1, 0);
        STEP(c3 + 2, 2, 1);
    }

#pragma unroll
    for (int mt = 0; mt < 4; mt++) {
#pragma unroll
        for (int nt = 0; nt < 4; nt++) {
            int row = m0 + wm * 64 + mt * 16 + lrow;
            int col = n0 + wn * 32 + nt * 8 + lcol * 2;
            float2 bv = *(const float2*)(bias + col);
            float2 o0, o1;
            o0.x = acc[mt][nt][0] + bv.x; o0.y = acc[mt][nt][1] + bv.y;
            o1.x = acc[mt][nt][2] + bv.x; o1.y = acc[mt][nt][3] + bv.y;
            *(float2*)(out + (size_t)row * ldc + col)       = o0;
            *(float2*)(out + (size_t)(row + 8) * ldc + col) = o1;
        }
    }
#undef STEP
#undef COMPUTE
#undef ISSUE
}

// ---------------------------------------------------------------------------
extern "C" void kernel_launch(void* const* d_in, const int* in_sizes, int n_in,
                              void* d_out, int out_size) {
    const float* x      = (const float*)d_in[0];
    const float* qkv_w  = (const float*)d_in[1];
    const float* qkv_b  = (const float*)d_in[2];
    const float* proj_w = (const float*)d_in[3];
    const float* proj_b = (const float*)d_in[4];
    const float* mlp_w1 = (const float*)d_in[5];
    const float* mlp_b1 = (const float*)d_in[6];
    const float* mlp_w2 = (const float*)d_in[7];
    const float* mlp_b2 = (const float*)d_in[8];

    float* wt_proj; cudaGetSymbolAddress((void**)&wt_proj, g_wt_proj);
    float* attn;    cudaGetSymbolAddress((void**)&attn,    g_attn);
    float* x32;     cudaGetSymbolAddress((void**)&x32,     g_x32);

    convert_x_kernel<<<(MTOT * CDIM / 4 + 255) / 256, 256>>>(x);
    transpose_qkv_kernel<<<dim3(3 * CDIM / 32, CDIM / 32), dim3(32, 8)>>>(qkv_w);
    transpose_kernel<<<dim3(CDIM / 32, CDIM / 32), dim3(32, 8)>>>(proj_w, wt_proj, CDIM, CDIM);
    bias_kernel<<<16, 256>>>(mlp_w1, mlp_b1, mlp_w2, mlp_b2);

    cudaFuncSetAttribute(qkv_attn_kernel, cudaFuncAttributeMaxDynamicSharedMemorySize, FUSED_SMEM);
    cudaFuncSetAttribute(gemm_tf32, cudaFuncAttributeMaxDynamicSharedMemorySize, GEMM_SMEM);

    // fused QKV GEMM + attention -> g_attn (tf32)
    qkv_attn_kernel<<<dim3(NH, MTOT / 128), 256, FUSED_SMEM>>>(x32, qkv_b);

    // projection GEMM: [131072,384] @ [384,384] -> d_out (fp32)
    gemm_tf32<<<dim3(3, MTOT / 128), 256, GEMM_SMEM>>>(attn, wt_proj, proj_b, (float*)d_out, CDIM);
}

// round 10
// speedup vs baseline: 2.1523x; 1.5359x over previous
#include <cuda_runtime.h>
#include <cuda_fp16.h>
#include <cstdint>
#include <math.h>

#define NWIN 2048
#define NTOK 64
#define CDIM 384
#define NH   12
#define HD   32
#define MTOT (NWIN * NTOK)

// ---------------------------------------------------------------------------
// Device scratch
// ---------------------------------------------------------------------------
__device__ __half g_x16[(size_t)MTOT * CDIM];           // x pre-rounded fp16
__device__ __half g_attn16[(size_t)MTOT * CDIM];        // attention out fp16
__device__ float  g_bias[NH * NTOK * NTOK];             // fp32
__device__ __half g_wt_qkv2h[(size_t)NH * 96 * CDIM];   // head-grouped [h][q|k|v][384]
__device__ __half g_wt_projh[(size_t)CDIM * CDIM];      // [384][384] K-major

__device__ __forceinline__ uint32_t h2u(__half2 h) { return *reinterpret_cast<uint32_t*>(&h); }

__device__ __forceinline__ void mma_f16(float* d, uint32_t a0, uint32_t a1, uint32_t a2,
                                        uint32_t a3, uint32_t b0, uint32_t b1) {
    asm volatile(
        "mma.sync.aligned.m16n8k16.row.col.f32.f16.f16.f32 "
        "{%0,%1,%2,%3}, {%4,%5,%6,%7}, {%8,%9}, {%0,%1,%2,%3};"
        : "+f"(d[0]), "+f"(d[1]), "+f"(d[2]), "+f"(d[3])
        : "r"(a0), "r"(a1), "r"(a2), "r"(a3), "r"(b0), "r"(b1));
}
__device__ __forceinline__ void ldsm4(uint32_t* r, uint32_t addr) {
    asm volatile("ldmatrix.sync.aligned.m8n8.x4.shared.b16 {%0,%1,%2,%3}, [%4];"
                 : "=r"(r[0]), "=r"(r[1]), "=r"(r[2]), "=r"(r[3]) : "r"(addr));
}
__device__ __forceinline__ uint32_t smem_u32(const void* p) {
    uint32_t a;
    asm("{ .reg .u64 t; cvta.to.shared.u64 t, %1; cvt.u32.u64 %0, t; }" : "=r"(a) : "l"(p));
    return a;
}
__device__ __forceinline__ void cp16(uint32_t dst, const void* src) {
    asm volatile("cp.async.cg.shared.global [%0], [%1], 16;" :: "r"(dst), "l"(src));
}
#define CP_COMMIT() asm volatile("cp.async.commit_group;" ::: "memory")
#define CP_WAIT(N)  asm volatile("cp.async.wait_group %0;" :: "n"(N) : "memory")

// ---------------------------------------------------------------------------
// x -> fp16
// ---------------------------------------------------------------------------
__global__ void convert_x_kernel(const float* __restrict__ in) {
    size_t i = ((size_t)blockIdx.x * blockDim.x + threadIdx.x) * 8;
    if (i >= (size_t)MTOT * CDIM) return;
    float4 v0 = *(const float4*)(in + i);
    float4 v1 = *(const float4*)(in + i + 4);
    uint4 o;
    o.x = h2u(__floats2half2_rn(v0.x, v0.y));
    o.y = h2u(__floats2half2_rn(v0.z, v0.w));
    o.z = h2u(__floats2half2_rn(v1.x, v1.y));
    o.w = h2u(__floats2half2_rn(v1.z, v1.w));
    *(uint4*)(g_x16 + i) = o;
}

// ---------------------------------------------------------------------------
// proj weight transpose + fp16:  out[N][K] = h(in[K][N])
// ---------------------------------------------------------------------------
__global__ void transpose_kernel(const float* __restrict__ in, __half* __restrict__ out,
                                 int K, int N) {
    __shared__ float tl[32][33];
    int n0 = blockIdx.x * 32, k0 = blockIdx.y * 32;
    int x = threadIdx.x, y = threadIdx.y;
#pragma unroll
    for (int j = y; j < 32; j += 8) tl[j][x] = in[(size_t)(k0 + j) * N + n0 + x];
    __syncthreads();
#pragma unroll
    for (int j = y; j < 32; j += 8) out[(size_t)(n0 + j) * K + k0 + x] = __float2half_rn(tl[x][j]);
}

// ---------------------------------------------------------------------------
// qkv weight transpose to head-grouped K-major fp16
// ---------------------------------------------------------------------------
__global__ void transpose_qkv_kernel(const float* __restrict__ in) {
    __shared__ float tl[32][33];
    int n0 = blockIdx.x * 32;
    int k0 = blockIdx.y * 32;
    int x = threadIdx.x, y = threadIdx.y;
#pragma unroll
    for (int j = y; j < 32; j += 8) tl[j][x] = in[(size_t)(k0 + j) * (3 * CDIM) + n0 + x];
    __syncthreads();
    int part = n0 / CDIM;
    int h    = (n0 % CDIM) / 32;
    int rbase = h * 96 + part * 32;
#pragma unroll
    for (int j = y; j < 32; j += 8)
        g_wt_qkv2h[(size_t)(rbase + j) * CDIM + k0 + x] = __float2half_rn(tl[x][j]);
}

// ---------------------------------------------------------------------------
// relative position bias table (fp32)
// ---------------------------------------------------------------------------
__global__ void bias_kernel(const float* __restrict__ w1, const float* __restrict__ b1,
                            const float* __restrict__ w2, const float* __restrict__ b2) {
    __shared__ float sw1[192], sb1[64], sw2[768], sb2[12];
    int tid = threadIdx.x;
    if (tid < 192) sw1[tid] = w1[tid];
    if (tid < 64)  sb1[tid] = b1[tid];
    for (int i = tid; i < 768; i += blockDim.x) sw2[i] = w2[i];
    if (tid < 12)  sb2[tid] = b2[tid];
    __syncthreads();

    int idx = blockIdx.x * blockDim.x + tid;
    if (idx >= NTOK * NTOK) return;
    int n = idx / NTOK, m = idx % NTOK;
    float r0 = (float)((n >> 4) & 3) - (float)((m >> 4) & 3);
    float r1 = (float)((n >> 2) & 3) - (float)((m >> 2) & 3);
    float r2 = (float)(n & 3)        - (float)(m & 3);

    float outh[NH];
#pragma unroll
    for (int h = 0; h < NH; h++) outh[h] = sb2[h];
    for (int j = 0; j < 64; j++) {
        float hj = fmaf(r0, sw1[j], fmaf(r1, sw1[64 + j], fmaf(r2, sw1[128 + j], sb1[j])));
        hj = fmaxf(hj, 0.0f);
#pragma unroll
        for (int h = 0; h < NH; h++) outh[h] = fmaf(hj, sw2[j * NH + h], outh[h]);
    }
#pragma unroll
    for (int h = 0; h < NH; h++) g_bias[h * NTOK * NTOK + idx] = outh[h];
}

// ---------------------------------------------------------------------------
// FUSED fp16 QKV-GEMM + attention. Grid (12, 1024), 256 thr, occ 2.
// GEMM: M=128 x N=96 x K=384 fp16; K-chunk 64 halfs (128B rows), 3-stage ring.
// 8 warps 4Mx2N, warp 32x48; m16n8k16.
// Attn staging (halfs): qs 2x[64][40] @0, ks @10240B, vt 2x[32][72] @20480B.
// ---------------------------------------------------------------------------
#define NCH 6
#define FUSED_SMEM 86016

__global__ void __launch_bounds__(256, 2)
qkv_attn_kernel(const __half* __restrict__ A, const float* __restrict__ qkv_b) {
    extern __shared__ float dsm[];
    __half* hsm = (__half*)dsm;

    const int t    = threadIdx.x;
    const int wid  = t >> 5, lane = t & 31;
    const int wm   = wid & 3;
    const int wn   = wid >> 2;
    const int h    = blockIdx.x;
    const int m0   = blockIdx.y * 128;
    const int lrow = lane >> 2;
    const int lcol = lane & 3;

    const uint32_t sbase = smem_u32(dsm);
    const __half* Bt = g_wt_qkv2h + (size_t)h * 96 * CDIM;

    float acc[2][6][4];
#pragma unroll
    for (int i = 0; i < 2; i++)
#pragma unroll
        for (int j = 0; j < 6; j++)
#pragma unroll
            for (int r = 0; r < 4; r++) acc[i][j][r] = 0.0f;

    const int ldr = t >> 3;            // 0..31
    const int ldg = t & 7;             // 16B group (8 halfs)

    const int grp = lane >> 3, lr8 = lane & 7;
    const int rsel = (grp & 1) * 8;    // +8-row selector
    const int ksel = grp >> 1;         // k 16B-group selector

    uint32_t aoff[2]; int arl[2];
#pragma unroll
    for (int mt = 0; mt < 2; mt++) {
        int r = wm * 32 + mt * 16 + rsel + lr8;
        aoff[mt] = (uint32_t)(r << 7);       // 128B rows
        arl[mt]  = r & 7;
    }
    uint32_t boff[3]; int brl[3];
#pragma unroll
    for (int p = 0; p < 3; p++) {
        int r = wn * 48 + p * 16 + rsel + lr8;
        boff[p] = (uint32_t)(r << 7);
        brl[p]  = r & 7;
    }

#define ISSUE(ch, st) do {                                                              \
        int _k0 = (ch) * 64;                                                            \
        _Pragma("unroll")                                                               \
        for (int _i = 0; _i < 4; _i++) {                                                \
            int _row = ldr + _i * 32;                                                   \
            int _sg  = ldg ^ (_row & 7);                                                \
            cp16(sbase + (st) * 16384 + (uint32_t)((_row << 7) + (_sg << 4)),           \
                 A + (size_t)(m0 + _row) * CDIM + _k0 + ldg * 8);                       \
        }                                                                               \
        _Pragma("unroll")                                                               \
        for (int _i = 0; _i < 3; _i++) {                                                \
            int _row = ldr + _i * 32;                                                   \
            int _sg  = ldg ^ (_row & 7);                                                \
            cp16(sbase + 49152 + (st) * 12288 + (uint32_t)((_row << 7) + (_sg << 4)),   \
                 Bt + (size_t)_row * CDIM + _k0 + ldg * 8);                             \
        }                                                                               \
        CP_COMMIT();                                                                    \
    } while (0)

#define COMPUTE(st) do {                                                                \
        const uint32_t Aab = sbase + (st) * 16384;                                      \
        const uint32_t Bab = sbase + 49152 + (st) * 12288;                              \
        _Pragma("unroll")                                                               \
        for (int ks = 0; ks < 4; ks++) {                                                \
            uint32_t afr[2][4], bfr[3][4];                                              \
            _Pragma("unroll")                                                           \
            for (int mt = 0; mt < 2; mt++)                                              \
                ldsm4(afr[mt], Aab + aoff[mt] +                                         \
                      (uint32_t)(((2 * ks + ksel) ^ arl[mt]) << 4));                    \
            _Pragma("unroll")                                                           \
            for (int p = 0; p < 3; p++)                                                 \
                ldsm4(bfr[p], Bab + boff[p] +                                           \
                      (uint32_t)(((2 * ks + ksel) ^ brl[p]) << 4));                     \
            _Pragma("unroll")                                                           \
            for (int mt = 0; mt < 2; mt++) {                                            \
                _Pragma("unroll")                                                       \
                for (int p = 0; p < 3; p++) {                                           \
                    mma_f16(acc[mt][2 * p],     afr[mt][0], afr[mt][1], afr[mt][2],     \
                            afr[mt][3], bfr[p][0], bfr[p][2]);                          \
                    mma_f16(acc[mt][2 * p + 1], afr[mt][0], afr[mt][1], afr[mt][2],     \
                            afr[mt][3], bfr[p][1], bfr[p][3]);                          \
                }                                                                       \
            }                                                                           \
        }                                                                               \
    } while (0)

#define STEP(c, st, stnext) do {                                                        \
        if ((c) == NCH - 1) { CP_WAIT(0); } else { CP_WAIT(1); }                        \
        __syncthreads();                                                                \
        if ((c) + 2 < NCH) ISSUE((c) + 2, stnext);                                      \
        COMPUTE(st);                                                                    \
    } while (0)

    ISSUE(0, 0);
    ISSUE(1, 1);
#pragma unroll
    for (int c3 = 0; c3 < NCH; c3 += 3) {
        STEP(c3 + 0, 0, 2);
        STEP(c3 + 1, 1, 0);
        STEP(c3 + 2, 2, 1);
    }

    // ---- epilogue: stage q/k/v (+bias, fp16) into smem union
    __half* qsh = hsm;                 // 2 x [64][40]
    __half* ksh = hsm + 5120;          // 2 x [64][40]
    __half* vth = hsm + 10240;         // 2 x [32][72]
    __syncthreads();
#pragma unroll
    for (int mt = 0; mt < 2; mt++) {
#pragma unroll
        for (int nt = 0; nt < 6; nt++) {
            int row = wm * 32 + mt * 16 + lrow;
            int col = wn * 48 + nt * 8 + lcol * 2;
            int part = col >> 5, c = col & 31;
            float2 bv = *(const float2*)(qkv_b + part * CDIM + h * HD + c);
            __half v00 = __float2half_rn(acc[mt][nt][0] + bv.x);
            __half v01 = __float2half_rn(acc[mt][nt][1] + bv.y);
            __half v10 = __float2half_rn(acc[mt][nt][2] + bv.x);
            __half v11 = __float2half_rn(acc[mt][nt][3] + bv.y);
            int tm = row >> 6, r64 = row & 63;
            if (part == 0) {
                __half* q_ = qsh + tm * 2560;
                q_[r64 * 40 + c] = v00; q_[r64 * 40 + c + 1] = v01;
                q_[(r64 + 8) * 40 + c] = v10; q_[(r64 + 8) * 40 + c + 1] = v11;
            } else if (part == 1) {
                __half* k_ = ksh + tm * 2560;
                k_[r64 * 40 + c] = v00; k_[r64 * 40 + c + 1] = v01;
                k_[(r64 + 8) * 40 + c] = v10; k_[(r64 + 8) * 40 + c + 1] = v11;
            } else {
                __half* v_ = vth + tm * 2304;
                v_[c * 72 + r64] = v00;       v_[(c + 1) * 72 + r64] = v01;
                v_[c * 72 + r64 + 8] = v10;   v_[(c + 1) * 72 + r64 + 8] = v11;
            }
        }
    }
    __syncthreads();

    // ---- attention: team = window (2 per CTA), 4 warps each
    const int team = wid >> 2;
    const int w    = wid & 3;
    const uint32_t qb = sbase + (uint32_t)(team * 5120);
    const uint32_t kb = sbase + 10240 + (uint32_t)(team * 5120);
    const uint32_t vb = sbase + 20480 + (uint32_t)(team * 4608);

    const float scale = 0.17677669529663687f;
    const int row0 = w * 16 + lrow;

    // q A-frag address (stride 80B); k/v B-frag addresses
    const uint32_t qrow = (uint32_t)((w * 16 + rsel + lr8) * 80);
    uint32_t krow[4];
#pragma unroll
    for (int p = 0; p < 4; p++) krow[p] = (uint32_t)((p * 16 + rsel + lr8) * 80);
    uint32_t vrow[2];
#pragma unroll
    for (int p = 0; p < 2; p++) vrow[p] = (uint32_t)((p * 16 + rsel + lr8) * 144);

    // ---- S = Q K^T (K=32: 2 ksteps)
    float sacc[8][4];
#pragma unroll
    for (int nt = 0; nt < 8; nt++)
#pragma unroll
        for (int r = 0; r < 4; r++) sacc[nt][r] = 0.0f;

#pragma unroll
    for (int kc = 0; kc < 2; kc++) {
        uint32_t af[4], bf[4][4];
        ldsm4(af, qb + qrow + (uint32_t)((2 * kc + ksel) << 4));
#pragma unroll
        for (int p = 0; p < 4; p++)
            ldsm4(bf[p], kb + krow[p] + (uint32_t)((2 * kc + ksel) << 4));
#pragma unroll
        for (int p = 0; p < 4; p++) {
            mma_f16(sacc[2 * p],     af[0], af[1], af[2], af[3], bf[p][0], bf[p][2]);
            mma_f16(sacc[2 * p + 1], af[0], af[1], af[2], af[3], bf[p][1], bf[p][3]);
        }
    }

    // scale + bias
    const float* bh = g_bias + h * NTOK * NTOK;
#pragma unroll
    for (int nt = 0; nt < 8; nt++) {
        int col = nt * 8 + lcol * 2;
        float2 b0 = *(const float2*)(bh + row0 * 64 + col);
        float2 b1 = *(const float2*)(bh + (row0 + 8) * 64 + col);
        sacc[nt][0] = fmaf(sacc[nt][0], scale, b0.x);
        sacc[nt][1] = fmaf(sacc[nt][1], scale, b0.y);
        sacc[nt][2] = fmaf(sacc[nt][2], scale, b1.x);
        sacc[nt][3] = fmaf(sacc[nt][3], scale, b1.y);
    }

    // register softmax (rows row0 / row0+8)
    {
        float mx0 = -1e30f, mx1 = -1e30f;
#pragma unroll
        for (int nt = 0; nt < 8; nt++) {
            mx0 = fmaxf(mx0, fmaxf(sacc[nt][0], sacc[nt][1]));
            mx1 = fmaxf(mx1, fmaxf(sacc[nt][2], sacc[nt][3]));
        }
        mx0 = fmaxf(mx0, __shfl_xor_sync(0xFFFFFFFFu, mx0, 1));
        mx0 = fmaxf(mx0, __shfl_xor_sync(0xFFFFFFFFu, mx0, 2));
        mx1 = fmaxf(mx1, __shfl_xor_sync(0xFFFFFFFFu, mx1, 1));
        mx1 = fmaxf(mx1, __shfl_xor_sync(0xFFFFFFFFu, mx1, 2));
        float s0 = 0.0f, s1 = 0.0f;
#pragma unroll
        for (int nt = 0; nt < 8; nt++) {
            sacc[nt][0] = __expf(sacc[nt][0] - mx0); s0 += sacc[nt][0];
            sacc[nt][1] = __expf(sacc[nt][1] - mx0); s0 += sacc[nt][1];
            sacc[nt][2] = __expf(sacc[nt][2] - mx1); s1 += sacc[nt][2];
            sacc[nt][3] = __expf(sacc[nt][3] - mx1); s1 += sacc[nt][3];
        }
        s0 += __shfl_xor_sync(0xFFFFFFFFu, s0, 1);
        s0 += __shfl_xor_sync(0xFFFFFFFFu, s0, 2);
        s1 += __shfl_xor_sync(0xFFFFFFFFu, s1, 1);
        s1 += __shfl_xor_sync(0xFFFFFFFFu, s1, 2);
        float i0 = 1.0f / s0, i1 = 1.0f / s1;
#pragma unroll
        for (int nt = 0; nt < 8; nt++) {
            sacc[nt][0] *= i0; sacc[nt][1] *= i0;
            sacc[nt][2] *= i1; sacc[nt][3] *= i1;
        }
    }

    // P -> fp16 A-fragments: acc layout == fp16 A-frag layout, no shfl!
    uint32_t pf[4][4];
#pragma unroll
    for (int kc = 0; kc < 4; kc++) {
        pf[kc][0] = h2u(__floats2half2_rn(sacc[2 * kc][0],     sacc[2 * kc][1]));
        pf[kc][1] = h2u(__floats2half2_rn(sacc[2 * kc][2],     sacc[2 * kc][3]));
        pf[kc][2] = h2u(__floats2half2_rn(sacc[2 * kc + 1][0], sacc[2 * kc + 1][1]));
        pf[kc][3] = h2u(__floats2half2_rn(sacc[2 * kc + 1][2], sacc[2 * kc + 1][3]));
    }

    // ---- O = P V (K=64: 4 ksteps)
    float oacc[4][4];
#pragma unroll
    for (int nt = 0; nt < 4; nt++)
#pragma unroll
        for (int r = 0; r < 4; r++) oacc[nt][r] = 0.0f;

#pragma unroll
    for (int kc = 0; kc < 4; kc++) {
        uint32_t vf[2][4];
#pragma unroll
        for (int p = 0; p < 2; p++)
            ldsm4(vf[p], vb + vrow[p] + (uint32_t)((2 * kc + ksel) << 4));
        mma_f16(oacc[0], pf[kc][0], pf[kc][1], pf[kc][2], pf[kc][3], vf[0][0], vf[0][2]);
        mma_f16(oacc[1], pf[kc][0], pf[kc][1], pf[kc][2], pf[kc][3], vf[0][1], vf[0][3]);
        mma_f16(oacc[2], pf[kc][0], pf[kc][1], pf[kc][2], pf[kc][3], vf[1][0], vf[1][2]);
        mma_f16(oacc[3], pf[kc][0], pf[kc][1], pf[kc][2], pf[kc][3], vf[1][1], vf[1][3]);
    }
    {
        __half* og = g_attn16 + (size_t)(m0 + team * 64) * CDIM + h * HD;
#pragma unroll
        for (int nt = 0; nt < 4; nt++) {
            int col = nt * 8 + lcol * 2;
            *(uint32_t*)(og + (size_t)row0 * CDIM + col) =
                h2u(__floats2half2_rn(oacc[nt][0], oacc[nt][1]));
            *(uint32_t*)(og + (size_t)(row0 + 8) * CDIM + col) =
                h2u(__floats2half2_rn(oacc[nt][2], oacc[nt][3]));
        }
    }
#undef STEP
#undef COMPUTE
#undef ISSUE
}

// ---------------------------------------------------------------------------
// proj GEMM fp16: CTA 128x128, 8 warps 2Mx4N, warp 64x32, K-chunk 64 halfs,
// 3-stage cp.async + ldmatrix, m16n8k16.
// ---------------------------------------------------------------------------
#define GEMM_SMEM (24576 * 4)   // 96 KB

__global__ void __launch_bounds__(256, 2)
gemm_f16(const __half* __restrict__ A, const __half* __restrict__ Bt,
         const float* __restrict__ bias, float* __restrict__ out, int ldc) {
    extern __shared__ float dsm[];

    const int t    = threadIdx.x;
    const int wid  = t >> 5, lane = t & 31;
    const int wm   = wid & 1;
    const int wn   = wid >> 1;
    const int n0   = blockIdx.x * 128;
    const int m0   = blockIdx.y * 128;
    const int lrow = lane >> 2;
    const int lcol = lane & 3;

    const uint32_t sbase = smem_u32(dsm);

    float acc[4][4][4];
#pragma unroll
    for (int i = 0; i < 4; i++)
#pragma unroll
        for (int j = 0; j < 4; j++)
#pragma unroll
            for (int r = 0; r < 4; r++) acc[i][j][r] = 0.0f;

    const int ldr = t >> 3;
    const int ldg = t & 7;

    const int grp = lane >> 3, lr8 = lane & 7;
    const int rsel = (grp & 1) * 8;
    const int ksel = grp >> 1;

    uint32_t aoff[4]; int arl[4];
#pragma unroll
    for (int mt = 0; mt < 4; mt++) {
        int r = wm * 64 + mt * 16 + rsel + lr8;
        aoff[mt] = (uint32_t)(r << 7);
        arl[mt]  = r & 7;
    }
    uint32_t boff[2]; int brl[2];
#pragma unroll
    for (int p = 0; p < 2; p++) {
        int r = wn * 32 + p * 16 + rsel + lr8;
        boff[p] = (uint32_t)(r << 7);
        brl[p]  = r & 7;
    }

#define ISSUE(ch, st) do {                                                              \
        int _k0 = (ch) * 64;                                                            \
        _Pragma("unroll")                                                               \
        for (int _i = 0; _i < 4; _i++) {                                                \
            int _row = ldr + _i * 32;                                                   \
            int _sg  = ldg ^ (_row & 7);                                                \
            uint32_t _off = (uint32_t)((st) * 16384 + (_row << 7) + (_sg << 4));        \
            cp16(sbase + _off,         A  + (size_t)(m0 + _row) * CDIM + _k0 + ldg * 8); \
            cp16(sbase + 49152 + _off, Bt + (size_t)(n0 + _row) * CDIM + _k0 + ldg * 8); \
        }                                                                               \
        CP_COMMIT();                                                                    \
    } while (0)

#define COMPUTE(st) do {                                                                \
        const uint32_t Aab = sbase + (st) * 16384;                                      \
        const uint32_t Bab = sbase + 49152 + (st) * 16384;                              \
        _Pragma("unroll")                                                               \
        for (int ks = 0; ks < 4; ks++) {                                                \
            uint32_t afr[4][4], bfr[2][4];                                              \
            _Pragma("unroll")                                                           \
            for (int mt = 0; mt < 4; mt++)                                              \
                ldsm4(afr[mt], Aab + aoff[mt] +                                         \
                      (uint32_t)(((2 * ks + ksel) ^ arl[mt]) << 4));                    \
            _Pragma("unroll")                                                           \
            for (int p = 0; p < 2; p++)                                                 \
                ldsm4(bfr[p], Bab + boff[p] +                                           \
                      (uint32_t)(((2 * ks + ksel) ^ brl[p]) << 4));                     \
            _Pragma("unroll")                                                           \
            for (int mt = 0; mt < 4; mt++) {                                            \
                mma_f16(acc[mt][0], afr[mt][0], afr[mt][1], afr[mt][2], afr[mt][3],     \
                        bfr[0][0], bfr[0][2]);                                          \
                mma_f16(acc[mt][1], afr[mt][0], afr[mt][1], afr[mt][2], afr[mt][3],     \
                        bfr[0][1], bfr[0][3]);                                          \
                mma_f16(acc[mt][2], afr[mt][0], afr[mt][1], afr[mt][2], afr[mt][3],     \
                        bfr[1][0], bfr[1][2]);                                          \
                mma_f16(acc[mt][3], afr[mt][0], afr[mt][1], afr[mt][2], afr[mt][3],     \
                        bfr[1][1], bfr[1][3]);                                          \
            }                                                                           \
        }                                                                               \
    } while (0)

#define STEP(c, st, stnext) do {                                                        \
        if ((c) == NCH - 1) { CP_WAIT(0); } else { CP_WAIT(1); }                        \
        __syncthreads();                                                                \
        if ((c) + 2 < NCH) ISSUE((c) + 2, stnext);                                      \
        COMPUTE(st);                                                                    \
    } while (0)

    ISSUE(0, 0);
    ISSUE(1, 1);
#pragma unroll
    for (int c3 = 0; c3 < NCH; c3 += 3) {
        STEP(c3 + 0, 0, 2);
        STEP(c3 + 1, 1, 0);
        STEP(c3 + 2, 2, 1);
    }

#pragma unroll
    for (int mt = 0; mt < 4; mt++) {
#pragma unroll
        for (int nt = 0; nt < 4; nt++) {
            int row = m0 + wm * 64 + mt * 16 + lrow;
            int col = n0 + wn * 32 + nt * 8 + lcol * 2;
            float2 bv = *(const float2*)(bias + col);
            float2 o0, o1;
            o0.x = acc[mt][nt][0] + bv.x; o0.y = acc[mt][nt][1] + bv.y;
            o1.x = acc[mt][nt][2] + bv.x; o1.y = acc[mt][nt][3] + bv.y;
            *(float2*)(out + (size_t)row * ldc + col)       = o0;
            *(float2*)(out + (size_t)(row + 8) * ldc + col) = o1;
        }
    }
#undef STEP
#undef COMPUTE
#undef ISSUE
}

// ---------------------------------------------------------------------------
extern "C" void kernel_launch(void* const* d_in, const int* in_sizes, int n_in,
                              void* d_out, int out_size) {
    const float* x      = (const float*)d_in[0];
    const float* qkv_w  = (const float*)d_in[1];
    const float* qkv_b  = (const float*)d_in[2];
    const float* proj_w = (const float*)d_in[3];
    const float* proj_b = (const float*)d_in[4];
    const float* mlp_w1 = (const float*)d_in[5];
    const float* mlp_b1 = (const float*)d_in[6];
    const float* mlp_w2 = (const float*)d_in[7];
    const float* mlp_b2 = (const float*)d_in[8];

    __half* wt_proj; cudaGetSymbolAddress((void**)&wt_proj, g_wt_projh);
    __half* attn;    cudaGetSymbolAddress((void**)&attn,    g_attn16);
    __half* x16;     cudaGetSymbolAddress((void**)&x16,     g_x16);

    convert_x_kernel<<<(MTOT * CDIM / 8 + 255) / 256, 256>>>(x);
    transpose_qkv_kernel<<<dim3(3 * CDIM / 32, CDIM / 32), dim3(32, 8)>>>(qkv_w);
    transpose_kernel<<<dim3(CDIM / 32, CDIM / 32), dim3(32, 8)>>>(proj_w, wt_proj, CDIM, CDIM);
    bias_kernel<<<16, 256>>>(mlp_w1, mlp_b1, mlp_w2, mlp_b2);

    cudaFuncSetAttribute(qkv_attn_kernel, cudaFuncAttributeMaxDynamicSharedMemorySize, FUSED_SMEM);
    cudaFuncSetAttribute(gemm_f16, cudaFuncAttributeMaxDynamicSharedMemorySize, GEMM_SMEM);

    // fused QKV GEMM + attention -> g_attn16 (fp16)
    qkv_attn_kernel<<<dim3(NH, MTOT / 128), 256, FUSED_SMEM>>>(x16, qkv_b);

    // projection GEMM: [131072,384] @ [384,384] -> d_out (fp32)
    gemm_f16<<<dim3(3, MTOT / 128), 256, GEMM_SMEM>>>(attn, wt_proj, proj_b, (float*)d_out, CDIM);
}

// round 11
// speedup vs baseline: 2.1908x; 1.0179x over previous
#include <cuda_runtime.h>
#include <cuda_fp16.h>
#include <cstdint>
#include <math.h>

#define NWIN 2048
#define NTOK 64
#define CDIM 384
#define NH   12
#define HD   32
#define MTOT (NWIN * NTOK)

// ---------------------------------------------------------------------------
// Device scratch
// ---------------------------------------------------------------------------
__device__ __half g_x16[(size_t)MTOT * CDIM];
__device__ __half g_attn16[(size_t)MTOT * CDIM];
__device__ float  g_bias[NH * NTOK * NTOK];
__device__ __half g_wt_qkv2h[(size_t)NH * 96 * CDIM];   // head-grouped [h][q|k|v][384]
__device__ __half g_wt_projh[(size_t)CDIM * CDIM];      // [384][384] K-major

__device__ __forceinline__ uint32_t h2u(__half2 h) { return *reinterpret_cast<uint32_t*>(&h); }

__device__ __forceinline__ void mma_f16(float* d, uint32_t a0, uint32_t a1, uint32_t a2,
                                        uint32_t a3, uint32_t b0, uint32_t b1) {
    asm volatile(
        "mma.sync.aligned.m16n8k16.row.col.f32.f16.f16.f32 "
        "{%0,%1,%2,%3}, {%4,%5,%6,%7}, {%8,%9}, {%0,%1,%2,%3};"
        : "+f"(d[0]), "+f"(d[1]), "+f"(d[2]), "+f"(d[3])
        : "r"(a0), "r"(a1), "r"(a2), "r"(a3), "r"(b0), "r"(b1));
}
__device__ __forceinline__ void ldsm4(uint32_t* r, uint32_t addr) {
    asm volatile("ldmatrix.sync.aligned.m8n8.x4.shared.b16 {%0,%1,%2,%3}, [%4];"
                 : "=r"(r[0]), "=r"(r[1]), "=r"(r[2]), "=r"(r[3]) : "r"(addr));
}
__device__ __forceinline__ uint32_t smem_u32(const void* p) {
    uint32_t a;
    asm("{ .reg .u64 t; cvta.to.shared.u64 t, %1; cvt.u32.u64 %0, t; }" : "=r"(a) : "l"(p));
    return a;
}
__device__ __forceinline__ void cp16(uint32_t dst, const void* src) {
    asm volatile("cp.async.cg.shared.global [%0], [%1], 16;" :: "r"(dst), "l"(src));
}
#define CP_COMMIT() asm volatile("cp.async.commit_group;" ::: "memory")
#define CP_WAIT(N)  asm volatile("cp.async.wait_group %0;" :: "n"(N) : "memory")

// ---------------------------------------------------------------------------
__global__ void convert_x_kernel(const float* __restrict__ in) {
    size_t i = ((size_t)blockIdx.x * blockDim.x + threadIdx.x) * 8;
    if (i >= (size_t)MTOT * CDIM) return;
    float4 v0 = *(const float4*)(in + i);
    float4 v1 = *(const float4*)(in + i + 4);
    uint4 o;
    o.x = h2u(__floats2half2_rn(v0.x, v0.y));
    o.y = h2u(__floats2half2_rn(v0.z, v0.w));
    o.z = h2u(__floats2half2_rn(v1.x, v1.y));
    o.w = h2u(__floats2half2_rn(v1.z, v1.w));
    *(uint4*)(g_x16 + i) = o;
}

__global__ void transpose_kernel(const float* __restrict__ in, __half* __restrict__ out,
                                 int K, int N) {
    __shared__ float tl[32][33];
    int n0 = blockIdx.x * 32, k0 = blockIdx.y * 32;
    int x = threadIdx.x, y = threadIdx.y;
#pragma unroll
    for (int j = y; j < 32; j += 8) tl[j][x] = in[(size_t)(k0 + j) * N + n0 + x];
    __syncthreads();
#pragma unroll
    for (int j = y; j < 32; j += 8) out[(size_t)(n0 + j) * K + k0 + x] = __float2half_rn(tl[x][j]);
}

__global__ void transpose_qkv_kernel(const float* __restrict__ in) {
    __shared__ float tl[32][33];
    int n0 = blockIdx.x * 32;
    int k0 = blockIdx.y * 32;
    int x = threadIdx.x, y = threadIdx.y;
#pragma unroll
    for (int j = y; j < 32; j += 8) tl[j][x] = in[(size_t)(k0 + j) * (3 * CDIM) + n0 + x];
    __syncthreads();
    int part = n0 / CDIM;
    int h    = (n0 % CDIM) / 32;
    int rbase = h * 96 + part * 32;
#pragma unroll
    for (int j = y; j < 32; j += 8)
        g_wt_qkv2h[(size_t)(rbase + j) * CDIM + k0 + x] = __float2half_rn(tl[x][j]);
}

__global__ void bias_kernel(const float* __restrict__ w1, const float* __restrict__ b1,
                            const float* __restrict__ w2, const float* __restrict__ b2) {
    __shared__ float sw1[192], sb1[64], sw2[768], sb2[12];
    int tid = threadIdx.x;
    if (tid < 192) sw1[tid] = w1[tid];
    if (tid < 64)  sb1[tid] = b1[tid];
    for (int i = tid; i < 768; i += blockDim.x) sw2[i] = w2[i];
    if (tid < 12)  sb2[tid] = b2[tid];
    __syncthreads();

    int idx = blockIdx.x * blockDim.x + tid;
    if (idx >= NTOK * NTOK) return;
    int n = idx / NTOK, m = idx % NTOK;
    float r0 = (float)((n >> 4) & 3) - (float)((m >> 4) & 3);
    float r1 = (float)((n >> 2) & 3) - (float)((m >> 2) & 3);
    float r2 = (float)(n & 3)        - (float)(m & 3);

    float outh[NH];
#pragma unroll
    for (int h = 0; h < NH; h++) outh[h] = sb2[h];
    for (int j = 0; j < 64; j++) {
        float hj = fmaf(r0, sw1[j], fmaf(r1, sw1[64 + j], fmaf(r2, sw1[128 + j], sb1[j])));
        hj = fmaxf(hj, 0.0f);
#pragma unroll
        for (int h = 0; h < NH; h++) outh[h] = fmaf(hj, sw2[j * NH + h], outh[h]);
    }
#pragma unroll
    for (int h = 0; h < NH; h++) g_bias[h * NTOK * NTOK + idx] = outh[h];
}

// ---------------------------------------------------------------------------
// FUSED fp16 QKV-GEMM + attention v2: 128 threads / 4 warps, warp tile 64x48
// (2Mx2N), 2-stage cp.async ring, occ 3. K-chunk 64 halfs (128B rows).
// smem: A 2x16KB @0, B 2x12KB @32768 -> 57344 B total.
// Attn staging (halfs, reuses ring): qs 2x[64][40] @0, ks @10240B,
//   vt 2x[32][72] @20480B (29696 B).
// ---------------------------------------------------------------------------
#define NCH 6
#define FUSED_SMEM 57344

__global__ void __launch_bounds__(128, 3)
qkv_attn_kernel(const __half* __restrict__ A, const float* __restrict__ qkv_b) {
    extern __shared__ float dsm[];
    __half* hsm = (__half*)dsm;

    const int t    = threadIdx.x;
    const int wid  = t >> 5, lane = t & 31;
    const int wm   = wid >> 1;         // 0..1 (64-row slab)
    const int wnn  = wid & 1;          // 0..1 (48-col slab)
    const int h    = blockIdx.x;
    const int m0   = blockIdx.y * 128;
    const int lrow = lane >> 2;
    const int lcol = lane & 3;

    const uint32_t sbase = smem_u32(dsm);
    const __half* Bt = g_wt_qkv2h + (size_t)h * 96 * CDIM;

    float acc[4][6][4];
#pragma unroll
    for (int i = 0; i < 4; i++)
#pragma unroll
        for (int j = 0; j < 6; j++)
#pragma unroll
            for (int r = 0; r < 4; r++) acc[i][j][r] = 0.0f;

    const int ldr = t >> 3;            // 0..15
    const int ldg = t & 7;

    const int grp = lane >> 3, lr8 = lane & 7;
    const int rsel = (grp & 1) * 8;
    const int ksel = grp >> 1;

    uint32_t aoff[4]; int arl[4];
#pragma unroll
    for (int mt = 0; mt < 4; mt++) {
        int r = wm * 64 + mt * 16 + rsel + lr8;
        aoff[mt] = (uint32_t)(r << 7);
        arl[mt]  = r & 7;
    }
    uint32_t boff[3]; int brl[3];
#pragma unroll
    for (int p = 0; p < 3; p++) {
        int r = wnn * 48 + p * 16 + rsel + lr8;
        boff[p] = (uint32_t)(r << 7);
        brl[p]  = r & 7;
    }

#define ISSUE(ch, st) do {                                                              \
        int _k0 = (ch) * 64;                                                            \
        _Pragma("unroll")                                                               \
        for (int _i = 0; _i < 8; _i++) {                                                \
            int _row = ldr + _i * 16;                                                   \
            int _sg  = ldg ^ (_row & 7);                                                \
            cp16(sbase + (st) * 16384 + (uint32_t)((_row << 7) + (_sg << 4)),           \
                 A + (size_t)(m0 + _row) * CDIM + _k0 + ldg * 8);                       \
        }                                                                               \
        _Pragma("unroll")                                                               \
        for (int _i = 0; _i < 6; _i++) {                                                \
            int _row = ldr + _i * 16;                                                   \
            int _sg  = ldg ^ (_row & 7);                                                \
            cp16(sbase + 32768 + (st) * 12288 + (uint32_t)((_row << 7) + (_sg << 4)),   \
                 Bt + (size_t)_row * CDIM + _k0 + ldg * 8);                             \
        }                                                                               \
        CP_COMMIT();                                                                    \
    } while (0)

#define COMPUTE(st) do {                                                                \
        const uint32_t Aab = sbase + (st) * 16384;                                      \
        const uint32_t Bab = sbase + 32768 + (st) * 12288;                              \
        _Pragma("unroll")                                                               \
        for (int ks = 0; ks < 4; ks++) {                                                \
            uint32_t afr[4][4], bfr[3][4];                                              \
            _Pragma("unroll")                                                           \
            for (int mt = 0; mt < 4; mt++)                                              \
                ldsm4(afr[mt], Aab + aoff[mt] +                                         \
                      (uint32_t)(((2 * ks + ksel) ^ arl[mt]) << 4));                    \
            _Pragma("unroll")                                                           \
            for (int p = 0; p < 3; p++)                                                 \
                ldsm4(bfr[p], Bab + boff[p] +                                           \
                      (uint32_t)(((2 * ks + ksel) ^ brl[p]) << 4));                     \
            _Pragma("unroll")                                                           \
            for (int mt = 0; mt < 4; mt++) {                                            \
                _Pragma("unroll")                                                       \
                for (int p = 0; p < 3; p++) {                                           \
                    mma_f16(acc[mt][2 * p],     afr[mt][0], afr[mt][1], afr[mt][2],     \
                            afr[mt][3], bfr[p][0], bfr[p][2]);                          \
                    mma_f16(acc[mt][2 * p + 1], afr[mt][0], afr[mt][1], afr[mt][2],     \
                            afr[mt][3], bfr[p][1], bfr[p][3]);                          \
                }                                                                       \
            }                                                                           \
        }                                                                               \
    } while (0)

#define STEP(c) do {                                                                    \
        if ((c) == NCH - 1) { CP_WAIT(0); } else { CP_WAIT(1); }                        \
        __syncthreads();                                                                \
        COMPUTE((c) & 1);                                                               \
        __syncthreads();                                                                \
        if ((c) + 2 < NCH) ISSUE((c) + 2, (c) & 1);                                     \
    } while (0)

    ISSUE(0, 0);
    ISSUE(1, 1);
    STEP(0); STEP(1); STEP(2); STEP(3); STEP(4); STEP(5);

    // ---- epilogue: stage q/k/v (+bias, fp16) into smem union
    __half* qsh = hsm;                 // 2 x [64][40]
    __half* ksh = hsm + 5120;          // 2 x [64][40]
    __half* vth = hsm + 10240;         // 2 x [32][72]
#pragma unroll
    for (int mt = 0; mt < 4; mt++) {
#pragma unroll
        for (int nt = 0; nt < 6; nt++) {
            int row = wm * 64 + mt * 16 + lrow;
            int col = wnn * 48 + nt * 8 + lcol * 2;
            int part = col >> 5, c = col & 31;
            float2 bv = *(const float2*)(qkv_b + part * CDIM + h * HD + c);
            __half v00 = __float2half_rn(acc[mt][nt][0] + bv.x);
            __half v01 = __float2half_rn(acc[mt][nt][1] + bv.y);
            __half v10 = __float2half_rn(acc[mt][nt][2] + bv.x);
            __half v11 = __float2half_rn(acc[mt][nt][3] + bv.y);
            int tm = row >> 6, r64 = row & 63;
            if (part == 0) {
                __half* q_ = qsh + tm * 2560;
                q_[r64 * 40 + c] = v00; q_[r64 * 40 + c + 1] = v01;
                q_[(r64 + 8) * 40 + c] = v10; q_[(r64 + 8) * 40 + c + 1] = v11;
            } else if (part == 1) {
                __half* k_ = ksh + tm * 2560;
                k_[r64 * 40 + c] = v00; k_[r64 * 40 + c + 1] = v01;
                k_[(r64 + 8) * 40 + c] = v10; k_[(r64 + 8) * 40 + c + 1] = v11;
            } else {
                __half* v_ = vth + tm * 2304;
                v_[c * 72 + r64] = v00;       v_[(c + 1) * 72 + r64] = v01;
                v_[c * 72 + r64 + 8] = v10;   v_[(c + 1) * 72 + r64 + 8] = v11;
            }
        }
    }
    __syncthreads();

    // ---- attention: 2 warps per window; warp owns 32 S-rows (2 m16 groups)
    const int team = wid >> 1;         // window 0/1
    const int w2   = wid & 1;          // row-half within window
    const uint32_t qb = sbase + (uint32_t)(team * 5120);
    const uint32_t kb = sbase + 10240 + (uint32_t)(team * 5120);
    const uint32_t vb = sbase + 20480 + (uint32_t)(team * 4608);

    const float scale = 0.17677669529663687f;

    uint32_t qrow[2];
#pragma unroll
    for (int g = 0; g < 2; g++) qrow[g] = (uint32_t)((w2 * 32 + g * 16 + rsel + lr8) * 80);
    uint32_t krow[4];
#pragma unroll
    for (int p = 0; p < 4; p++) krow[p] = (uint32_t)((p * 16 + rsel + lr8) * 80);
    uint32_t vrow[2];
#pragma unroll
    for (int p = 0; p < 2; p++) vrow[p] = (uint32_t)((p * 16 + rsel + lr8) * 144);

    // ---- S = Q K^T  (2 row-groups x 64 cols, K=32: 2 ksteps)
    float sacc[2][8][4];
#pragma unroll
    for (int g = 0; g < 2; g++)
#pragma unroll
        for (int nt = 0; nt < 8; nt++)
#pragma unroll
            for (int r = 0; r < 4; r++) sacc[g][nt][r] = 0.0f;

#pragma unroll
    for (int kc = 0; kc < 2; kc++) {
        uint32_t af[2][4], bf[4][4];
#pragma unroll
        for (int g = 0; g < 2; g++)
            ldsm4(af[g], qb + qrow[g] + (uint32_t)((2 * kc + ksel) << 4));
#pragma unroll
        for (int p = 0; p < 4; p++)
            ldsm4(bf[p], kb + krow[p] + (uint32_t)((2 * kc + ksel) << 4));
#pragma unroll
        for (int g = 0; g < 2; g++)
#pragma unroll
            for (int p = 0; p < 4; p++) {
                mma_f16(sacc[g][2 * p],     af[g][0], af[g][1], af[g][2], af[g][3],
                        bf[p][0], bf[p][2]);
                mma_f16(sacc[g][2 * p + 1], af[g][0], af[g][1], af[g][2], af[g][3],
                        bf[p][1], bf[p][3]);
            }
    }

    // scale + bias + register softmax per group
    const float* bh = g_bias + h * NTOK * NTOK;
#pragma unroll
    for (int g = 0; g < 2; g++) {
        int row0 = w2 * 32 + g * 16 + lrow;
#pragma unroll
        for (int nt = 0; nt < 8; nt++) {
            int col = nt * 8 + lcol * 2;
            float2 b0 = *(const float2*)(bh + row0 * 64 + col);
            float2 b1 = *(const float2*)(bh + (row0 + 8) * 64 + col);
            sacc[g][nt][0] = fmaf(sacc[g][nt][0], scale, b0.x);
            sacc[g][nt][1] = fmaf(sacc[g][nt][1], scale, b0.y);
            sacc[g][nt][2] = fmaf(sacc[g][nt][2], scale, b1.x);
            sacc[g][nt][3] = fmaf(sacc[g][nt][3], scale, b1.y);
        }
        float mx0 = -1e30f, mx1 = -1e30f;
#pragma unroll
        for (int nt = 0; nt < 8; nt++) {
            mx0 = fmaxf(mx0, fmaxf(sacc[g][nt][0], sacc[g][nt][1]));
            mx1 = fmaxf(mx1, fmaxf(sacc[g][nt][2], sacc[g][nt][3]));
        }
        mx0 = fmaxf(mx0, __shfl_xor_sync(0xFFFFFFFFu, mx0, 1));
        mx0 = fmaxf(mx0, __shfl_xor_sync(0xFFFFFFFFu, mx0, 2));
        mx1 = fmaxf(mx1, __shfl_xor_sync(0xFFFFFFFFu, mx1, 1));
        mx1 = fmaxf(mx1, __shfl_xor_sync(0xFFFFFFFFu, mx1, 2));
        float s0 = 0.0f, s1 = 0.0f;
#pragma unroll
        for (int nt = 0; nt < 8; nt++) {
            sacc[g][nt][0] = __expf(sacc[g][nt][0] - mx0); s0 += sacc[g][nt][0];
            sacc[g][nt][1] = __expf(sacc[g][nt][1] - mx0); s0 += sacc[g][nt][1];
            sacc[g][nt][2] = __expf(sacc[g][nt][2] - mx1); s1 += sacc[g][nt][2];
            sacc[g][nt][3] = __expf(sacc[g][nt][3] - mx1); s1 += sacc[g][nt][3];
        }
        s0 += __shfl_xor_sync(0xFFFFFFFFu, s0, 1);
        s0 += __shfl_xor_sync(0xFFFFFFFFu, s0, 2);
        s1 += __shfl_xor_sync(0xFFFFFFFFu, s1, 1);
        s1 += __shfl_xor_sync(0xFFFFFFFFu, s1, 2);
        float i0 = 1.0f / s0, i1 = 1.0f / s1;
#pragma unroll
        for (int nt = 0; nt < 8; nt++) {
            sacc[g][nt][0] *= i0; sacc[g][nt][1] *= i0;
            sacc[g][nt][2] *= i1; sacc[g][nt][3] *= i1;
        }
    }

    // P -> fp16 A-fragments (acc layout == A-frag layout)
    uint32_t pf[2][4][4];
#pragma unroll
    for (int g = 0; g < 2; g++)
#pragma unroll
        for (int kc = 0; kc < 4; kc++) {
            pf[g][kc][0] = h2u(__floats2half2_rn(sacc[g][2 * kc][0],     sacc[g][2 * kc][1]));
            pf[g][kc][1] = h2u(__floats2half2_rn(sacc[g][2 * kc][2],     sacc[g][2 * kc][3]));
            pf[g][kc][2] = h2u(__floats2half2_rn(sacc[g][2 * kc + 1][0], sacc[g][2 * kc + 1][1]));
            pf[g][kc][3] = h2u(__floats2half2_rn(sacc[g][2 * kc + 1][2], sacc[g][2 * kc + 1][3]));
        }

    // ---- O = P V (K=64: 4 ksteps; V frags shared across groups)
    float oacc[2][4][4];
#pragma unroll
    for (int g = 0; g < 2; g++)
#pragma unroll
        for (int nt = 0; nt < 4; nt++)
#pragma unroll
            for (int r = 0; r < 4; r++) oacc[g][nt][r] = 0.0f;

#pragma unroll
    for (int kc = 0; kc < 4; kc++) {
        uint32_t vf[2][4];
#pragma unroll
        for (int p = 0; p < 2; p++)
            ldsm4(vf[p], vb + vrow[p] + (uint32_t)((2 * kc + ksel) << 4));
#pragma unroll
        for (int g = 0; g < 2; g++) {
            mma_f16(oacc[g][0], pf[g][kc][0], pf[g][kc][1], pf[g][kc][2], pf[g][kc][3],
                    vf[0][0], vf[0][2]);
            mma_f16(oacc[g][1], pf[g][kc][0], pf[g][kc][1], pf[g][kc][2], pf[g][kc][3],
                    vf[0][1], vf[0][3]);
            mma_f16(oacc[g][2], pf[g][kc][0], pf[g][kc][1], pf[g][kc][2], pf[g][kc][3],
                    vf[1][0], vf[1][2]);
            mma_f16(oacc[g][3], pf[g][kc][0], pf[g][kc][1], pf[g][kc][2], pf[g][kc][3],
                    vf[1][1], vf[1][3]);
        }
    }
    {
        __half* og = g_attn16 + (size_t)(m0 + team * 64) * CDIM + h * HD;
#pragma unroll
        for (int g = 0; g < 2; g++) {
            int row0 = w2 * 32 + g * 16 + lrow;
#pragma unroll
            for (int nt = 0; nt < 4; nt++) {
                int col = nt * 8 + lcol * 2;
                *(uint32_t*)(og + (size_t)row0 * CDIM + col) =
                    h2u(__floats2half2_rn(oacc[g][nt][0], oacc[g][nt][1]));
                *(uint32_t*)(og + (size_t)(row0 + 8) * CDIM + col) =
                    h2u(__floats2half2_rn(oacc[g][nt][2], oacc[g][nt][3]));
            }
        }
    }
#undef STEP
#undef COMPUTE
#undef ISSUE
}

// ---------------------------------------------------------------------------
// proj GEMM fp16 (unchanged, proven): CTA 128x128, 8 warps 2Mx4N, warp 64x32,
// K-chunk 64 halfs, 3-stage cp.async + ldmatrix.
// ---------------------------------------------------------------------------
#define PNCH 6
#define GEMM_SMEM (24576 * 4)

__global__ void __launch_bounds__(256, 2)
gemm_f16(const __half* __restrict__ A, const __half* __restrict__ Bt,
         const float* __restrict__ bias, float* __restrict__ out, int ldc) {
    extern __shared__ float dsm[];

    const int t    = threadIdx.x;
    const int wid  = t >> 5, lane = t & 31;
    const int wm   = wid & 1;
    const int wn   = wid >> 1;
    const int n0   = blockIdx.x * 128;
    const int m0   = blockIdx.y * 128;
    const int lrow = lane >> 2;
    const int lcol = lane & 3;

    const uint32_t sbase = smem_u32(dsm);

    float acc[4][4][4];
#pragma unroll
    for (int i = 0; i < 4; i++)
#pragma unroll
        for (int j = 0; j < 4; j++)
#pragma unroll
            for (int r = 0; r < 4; r++) acc[i][j][r] = 0.0f;

    const int ldr = t >> 3;
    const int ldg = t & 7;

    const int grp = lane >> 3, lr8 = lane & 7;
    const int rsel = (grp & 1) * 8;
    const int ksel = grp >> 1;

    uint32_t aoff[4]; int arl[4];
#pragma unroll
    for (int mt = 0; mt < 4; mt++) {
        int r = wm * 64 + mt * 16 + rsel + lr8;
        aoff[mt] = (uint32_t)(r << 7);
        arl[mt]  = r & 7;
    }
    uint32_t boff[2]; int brl[2];
#pragma unroll
    for (int p = 0; p < 2; p++) {
        int r = wn * 32 + p * 16 + rsel + lr8;
        boff[p] = (uint32_t)(r << 7);
        brl[p]  = r & 7;
    }

#define ISSUE(ch, st) do {                                                              \
        int _k0 = (ch) * 64;                                                            \
        _Pragma("unroll")                                                               \
        for (int _i = 0; _i < 4; _i++) {                                                \
            int _row = ldr + _i * 32;                                                   \
            int _sg  = ldg ^ (_row & 7);                                                \
            uint32_t _off = (uint32_t)((st) * 16384 + (_row << 7) + (_sg << 4));        \
            cp16(sbase + _off,         A  + (size_t)(m0 + _row) * CDIM + _k0 + ldg * 8); \
            cp16(sbase + 49152 + _off, Bt + (size_t)(n0 + _row) * CDIM + _k0 + ldg * 8); \
        }                                                                               \
        CP_COMMIT();                                                                    \
    } while (0)

#define COMPUTE(st) do {                                                                \
        const uint32_t Aab = sbase + (st) * 16384;                                      \
        const uint32_t Bab = sbase + 49152 + (st) * 16384;                              \
        _Pragma("unroll")                                                               \
        for (int ks = 0; ks < 4; ks++) {                                                \
            uint32_t afr[4][4], bfr[2][4];                                              \
            _Pragma("unroll")                                                           \
            for (int mt = 0; mt < 4; mt++)                                              \
                ldsm4(afr[mt], Aab + aoff[mt] +                                         \
                      (uint32_t)(((2 * ks + ksel) ^ arl[mt]) << 4));                    \
            _Pragma("unroll")                                                           \
            for (int p = 0; p < 2; p++)                                                 \
                ldsm4(bfr[p], Bab + boff[p] +                                           \
                      (uint32_t)(((2 * ks + ksel) ^ brl[p]) << 4));                     \
            _Pragma("unroll")                                                           \
            for (int mt = 0; mt < 4; mt++) {                                            \
                mma_f16(acc[mt][0], afr[mt][0], afr[mt][1], afr[mt][2], afr[mt][3],     \
                        bfr[0][0], bfr[0][2]);                                          \
                mma_f16(acc[mt][1], afr[mt][0], afr[mt][1], afr[mt][2], afr[mt][3],     \
                        bfr[0][1], bfr[0][3]);                                          \
                mma_f16(acc[mt][2], afr[mt][0], afr[mt][1], afr[mt][2], afr[mt][3],     \
                        bfr[1][0], bfr[1][2]);                                          \
                mma_f16(acc[mt][3], afr[mt][0], afr[mt][1], afr[mt][2], afr[mt][3],     \
                        bfr[1][1], bfr[1][3]);                                          \
            }                                                                           \
        }                                                                               \
    } while (0)

#define STEP(c, st, stnext) do {                                                        \
        if ((c) == PNCH - 1) { CP_WAIT(0); } else { CP_WAIT(1); }                       \
        __syncthreads();                                                                \
        if ((c) + 2 < PNCH) ISSUE((c) + 2, stnext);                                     \
        COMPUTE(st);                                                                    \
    } while (0)

    ISSUE(0, 0);
    ISSUE(1, 1);
#pragma unroll
    for (int c3 = 0; c3 < PNCH; c3 += 3) {
        STEP(c3 + 0, 0, 2);
        STEP(c3 + 1, 1, 0);
        STEP(c3 + 2, 2, 1);
    }

#pragma unroll
    for (int mt = 0; mt < 4; mt++) {
#pragma unroll
        for (int nt = 0; nt < 4; nt++) {
            int row = m0 + wm * 64 + mt * 16 + lrow;
            int col = n0 + wn * 32 + nt * 8 + lcol * 2;
            float2 bv = *(const float2*)(bias + col);
            float2 o0, o1;
            o0.x = acc[mt][nt][0] + bv.x; o0.y = acc[mt][nt][1] + bv.y;
            o1.x = acc[mt][nt][2] + bv.x; o1.y = acc[mt][nt][3] + bv.y;
            *(float2*)(out + (size_t)row * ldc + col)       = o0;
            *(float2*)(out + (size_t)(row + 8) * ldc + col) = o1;
        }
    }
#undef STEP
#undef COMPUTE
#undef ISSUE
}

// ---------------------------------------------------------------------------
extern "C" void kernel_launch(void* const* d_in, const int* in_sizes, int n_in,
                              void* d_out, int out_size) {
    const float* x      = (const float*)d_in[0];
    const float* qkv_w  = (const float*)d_in[1];
    const float* qkv_b  = (const float*)d_in[2];
    const float* proj_w = (const float*)d_in[3];
    const float* proj_b = (const float*)d_in[4];
    const float* mlp_w1 = (const float*)d_in[5];
    const float* mlp_b1 = (const float*)d_in[6];
    const float* mlp_w2 = (const float*)d_in[7];
    const float* mlp_b2 = (const float*)d_in[8];

    __half* wt_proj; cudaGetSymbolAddress((void**)&wt_proj, g_wt_projh);
    __half* attn;    cudaGetSymbolAddress((void**)&attn,    g_attn16);
    __half* x16;     cudaGetSymbolAddress((void**)&x16,     g_x16);

    convert_x_kernel<<<(MTOT * CDIM / 8 + 255) / 256, 256>>>(x);
    transpose_qkv_kernel<<<dim3(3 * CDIM / 32, CDIM / 32), dim3(32, 8)>>>(qkv_w);
    transpose_kernel<<<dim3(CDIM / 32, CDIM / 32), dim3(32, 8)>>>(proj_w, wt_proj, CDIM, CDIM);
    bias_kernel<<<16, 256>>>(mlp_w1, mlp_b1, mlp_w2, mlp_b2);

    cudaFuncSetAttribute(qkv_attn_kernel, cudaFuncAttributeMaxDynamicSharedMemorySize, FUSED_SMEM);
    cudaFuncSetAttribute(gemm_f16, cudaFuncAttributeMaxDynamicSharedMemorySize, GEMM_SMEM);

    // fused QKV GEMM + attention -> g_attn16 (fp16)
    qkv_attn_kernel<<<dim3(NH, MTOT / 128), 128, FUSED_SMEM>>>(x16, qkv_b);

    // projection GEMM: [131072,384] @ [384,384] -> d_out (fp32)
    gemm_f16<<<dim3(3, MTOT / 128), 256, GEMM_SMEM>>>(attn, wt_proj, proj_b, (float*)d_out, CDIM);
}